// round 6
// baseline (speedup 1.0000x reference)
#include <cuda_runtime.h>
#include <math.h>
#include <stdint.h>

// ---------------- problem constants ----------------
#define LNUM 2
#define BB   4
#define TT   1000
#define CC   768
#define HH   12
#define DKK  64
#define WHALF 50         // band half-width (WIN//2)
#define NR   101         // relative positions actually reachable: -50..50
#define BT   (BB*TT)     // 4000 rows

// ---------------- device scratch (no allocs allowed) ----------------
__device__ float g_h[BT*CC];
__device__ float g_y[BT*CC];
__device__ float g_q[BT*CC];
__device__ float g_k[BT*CC];
__device__ float g_v[BT*CC];
__device__ float g_o[BT*CC];
__device__ float g_pe[NR*CC];   // central 101 rows of the rel-pos table
__device__ float g_pc[NR*CC];   // pe_cen @ Wp[l]

// ---------------- init: h = x * sqrt(C) ----------------
__global__ void init_h_kernel(const float* __restrict__ x) {
    int i = blockIdx.x * blockDim.x + threadIdx.x;
    if (i < BT*CC) g_h[i] = x[i] * 27.712812921102035f;  // sqrt(768)
}

// ---------------- positional table (central 101 rows only) ----------------
__global__ void pe_kernel() {
    int i = blockIdx.x * blockDim.x + threadIdx.x;
    if (i < NR*(CC/2)) {
        int r = i / (CC/2);
        int j = i % (CC/2);
        float div = expf(-(float)(2*j) * (9.210340371976184f / (float)CC)); // ln(10000)/C
        float ang = (float)(WHALF - r) * div;   // rel = -(r-50)
        g_pe[r*CC + 2*j]     = sinf(ang);
        g_pe[r*CC + 2*j + 1] = cosf(ang);
    }
}

// ---------------- LayerNorm (one block per row) ----------------
__global__ void ln_kernel(const float* __restrict__ in, float* __restrict__ out,
                          const float* __restrict__ g, const float* __restrict__ b) {
    int row = blockIdx.x;
    const float* xr = in + (size_t)row * CC;
    float s = 0.f, s2 = 0.f;
    for (int i = threadIdx.x; i < CC; i += 256) {
        float v = xr[i];
        s += v; s2 += v * v;
    }
    __shared__ float sh[16];
    #pragma unroll
    for (int o = 16; o; o >>= 1) {
        s  += __shfl_xor_sync(0xffffffffu, s,  o);
        s2 += __shfl_xor_sync(0xffffffffu, s2, o);
    }
    int w = threadIdx.x >> 5;
    if ((threadIdx.x & 31) == 0) { sh[w] = s; sh[8 + w] = s2; }
    __syncthreads();
    s = 0.f; s2 = 0.f;
    #pragma unroll
    for (int i = 0; i < 8; i++) { s += sh[i]; s2 += sh[8 + i]; }
    float mean = s * (1.f / CC);
    float var  = s2 * (1.f / CC) - mean * mean;
    float rstd = rsqrtf(var + 1e-5f);
    float* orow = out + (size_t)row * CC;
    for (int i = threadIdx.x; i < CC; i += 256)
        orow[i] = (xr[i] - mean) * rstd * g[i] + b[i];
}

// ---------------- tf32 tensor-core GEMM ----------------
// C(MxN) = A(MxK) @ B(KxN) [+bias] [epilogue], fp32 accumulate, tf32 inputs.
// BM=128, BN=64, BK=16. 256 threads = 8 warps in 4x2 grid; warp tile 32x32.
// Smem holds PRE-PACKED mma fragments (conflict-free STS and LDS):
//   Asf[buf][mt*2+ch][lane*4 + reg]  (uint4 per lane)   16 groups (mt 0..7)
//   Bsf[buf][nt*2+ch][lane*2 + reg]  (uint2 per lane)   16 groups (nt 0..7)
// tf32 trick: feed raw f32 bits; HMMA tf32 reads only the high mantissa bits
// (effective round-to-zero). No cvt instructions.
// EPI: 0 = none, 1 = gelu(tanh), 2 = += resid

__device__ __forceinline__ void mma_tf32(float c[4], const uint4& a, const uint2& b) {
    asm volatile(
        "mma.sync.aligned.m16n8k8.row.col.f32.tf32.tf32.f32 "
        "{%0,%1,%2,%3}, {%4,%5,%6,%7}, {%8,%9}, {%0,%1,%2,%3};"
        : "+f"(c[0]), "+f"(c[1]), "+f"(c[2]), "+f"(c[3])
        : "r"(a.x), "r"(a.y), "r"(a.z), "r"(a.w), "r"(b.x), "r"(b.y));
}

__device__ __forceinline__ float gelu_f(float x) {
    float x3 = x * x * x;
    return 0.5f * x * (1.f + tanhf(0.7978845608028654f * (x + 0.044715f * x3)));
}

template<int EPI>
__device__ __forceinline__ void gemm_body(
        const float* __restrict__ A, const float* __restrict__ Bm,
        const float* __restrict__ bias, const float* __restrict__ resid,
        float* __restrict__ Cm, int M, int N, int K, int row0, int col0) {
    __shared__ uint32_t Asf[2][16][128];   // 16 KB
    __shared__ uint32_t Bsf[2][16][64];    //  8 KB

    const int tid  = threadIdx.x;
    const int warp = tid >> 5;
    const int lane = tid & 31;
    const int g    = lane >> 2;    // 0..7
    const int t    = lane & 3;     // 0..3
    const int wr   = warp >> 1;    // 0..3 : warp row (32 M-rows each)
    const int wc   = warp & 1;     // 0..1 : warp col (32 N-cols each)

    float acc[2][4][4];
    #pragma unroll
    for (int i = 0; i < 2; i++)
        #pragma unroll
        for (int j = 0; j < 4; j++)
            #pragma unroll
            for (int r = 0; r < 4; r++) acc[i][j][r] = 0.f;

    uint32_t ra[2][4];
    uint32_t rb[2][2];

    // Producer: warp w fills groups {2w, 2w+1} of both A and B fragment arrays.
#define LOAD_TILES(k0) do {                                                          \
        _Pragma("unroll")                                                            \
        for (int q2 = 0; q2 < 2; q2++) {                                             \
            int grp = warp * 2 + q2;                                                 \
            int mt = grp >> 1, ch = grp & 1;                                         \
            int m0 = mt * 16 + g;                                                    \
            const float* ab = A + (size_t)(row0 + m0) * K + (k0) + ch * 8 + t;       \
            bool v0 = (row0 + m0)     < M;                                           \
            bool v1 = (row0 + m0 + 8) < M;                                           \
            ra[q2][0] = v0 ? __float_as_uint(ab[0]) : 0u;                            \
            ra[q2][1] = v1 ? __float_as_uint(ab[(size_t)8 * K]) : 0u;                \
            ra[q2][2] = v0 ? __float_as_uint(ab[4]) : 0u;                            \
            ra[q2][3] = v1 ? __float_as_uint(ab[(size_t)8 * K + 4]) : 0u;            \
            const float* bb = Bm + (size_t)((k0) + ch * 8 + t) * N + col0 + mt * 8 + g; \
            rb[q2][0] = __float_as_uint(bb[0]);                                      \
            rb[q2][1] = __float_as_uint(bb[(size_t)4 * N]);                          \
        }                                                                            \
    } while (0)

    LOAD_TILES(0);
    const int steps = K >> 4;
    for (int s = 0; s < steps; s++) {
        const int buf = s & 1;
        #pragma unroll
        for (int q2 = 0; q2 < 2; q2++) {
            *(uint4*)&Asf[buf][warp * 2 + q2][lane * 4] =
                make_uint4(ra[q2][0], ra[q2][1], ra[q2][2], ra[q2][3]);
            *(uint2*)&Bsf[buf][warp * 2 + q2][lane * 2] =
                make_uint2(rb[q2][0], rb[q2][1]);
        }
        __syncthreads();
        if (s + 1 < steps) LOAD_TILES((s + 1) * 16);
        #pragma unroll
        for (int ch = 0; ch < 2; ch++) {
            uint4 af[2];
            uint2 bf[4];
            #pragma unroll
            for (int i = 0; i < 2; i++)
                af[i] = *(const uint4*)&Asf[buf][(wr * 2 + i) * 2 + ch][lane * 4];
            #pragma unroll
            for (int j = 0; j < 4; j++)
                bf[j] = *(const uint2*)&Bsf[buf][(wc * 4 + j) * 2 + ch][lane * 2];
            #pragma unroll
            for (int i = 0; i < 2; i++)
                #pragma unroll
                for (int j = 0; j < 4; j++)
                    mma_tf32(acc[i][j], af[i], bf[j]);
        }
        __syncthreads();
    }
#undef LOAD_TILES

    // epilogue: c0/c1 at (row g, cols 2t/2t+1), c2/c3 at row g+8
    #pragma unroll
    for (int i = 0; i < 2; i++) {
        int rbase = row0 + wr * 32 + i * 16 + g;
        #pragma unroll
        for (int j = 0; j < 4; j++) {
            int col = col0 + wc * 32 + j * 8 + t * 2;
            float bx = 0.f, by = 0.f;
            if (bias) { bx = bias[col]; by = bias[col + 1]; }
            #pragma unroll
            for (int hh = 0; hh < 2; hh++) {
                int row = rbase + hh * 8;
                if (row < M) {
                    float c0 = acc[i][j][hh * 2 + 0] + bx;
                    float c1 = acc[i][j][hh * 2 + 1] + by;
                    if (EPI == 1) { c0 = gelu_f(c0); c1 = gelu_f(c1); }
                    if (EPI == 2) {
                        float2 rv = *(const float2*)(resid + (size_t)row * N + col);
                        c0 += rv.x; c1 += rv.y;
                    }
                    *(float2*)(Cm + (size_t)row * N + col) = make_float2(c0, c1);
                }
            }
        }
    }
}

template<int EPI>
__global__ void __launch_bounds__(256, 2)
tgemm_kernel(const float* __restrict__ A, const float* __restrict__ Bm,
             const float* __restrict__ bias, const float* __restrict__ resid,
             float* __restrict__ Cm, int M, int N, int K) {
    gemm_body<EPI>(A, Bm, bias, resid, Cm, M, N, K,
                   blockIdx.y * 128, blockIdx.x * 64);
}

// fused QKV: blockIdx.x in [0, 36); sel = x/12 picks {q,k,v}
__global__ void __launch_bounds__(256, 2)
qkv_kernel(const float* __restrict__ A,
           const float* __restrict__ Bq, const float* __restrict__ Bk,
           const float* __restrict__ Bv,
           const float* __restrict__ bq, const float* __restrict__ bk,
           const float* __restrict__ bv,
           float* __restrict__ Cq, float* __restrict__ Ck, float* __restrict__ Cv) {
    int sel = blockIdx.x / 12;
    int colblk = blockIdx.x % 12;
    const float* Bm   = (sel == 0) ? Bq : (sel == 1) ? Bk : Bv;
    const float* bias = (sel == 0) ? bq : (sel == 1) ? bk : bv;
    float*       Cm   = (sel == 0) ? Cq : (sel == 1) ? Ck : Cv;
    gemm_body<0>(A, Bm, bias, nullptr, Cm, BT, CC, CC,
                 blockIdx.y * 128, colblk * 64);
}

// ---------------- banded rel-pos attention ----------------
#define TQ 16
#define SR (TQ + 2*WHALF)   // 116 k/v rows staged

__global__ void __launch_bounds__(256)
attn_kernel(const float* __restrict__ q, const float* __restrict__ k,
            const float* __restrict__ v, const float* __restrict__ pc,
            const float* __restrict__ pu, const float* __restrict__ pv,
            float* __restrict__ o) {
    __shared__ __align__(16) float ks[SR * 65];   // k tile, later reused for v tile
    __shared__ float qu[TQ * 65];
    __shared__ float qv[TQ * 65];
    __shared__ float sc[TQ * 104];

    int b  = blockIdx.z;
    int h  = blockIdx.y;
    int t0 = blockIdx.x * TQ;
    int sbase = t0 - WHALF;
    int tid = threadIdx.x;

    for (int e = tid; e < TQ * DKK; e += 256) {
        int qi = e >> 6, d = e & 63;
        int t = t0 + qi;
        float val = (t < TT) ? q[((size_t)(b * TT + t)) * CC + h * DKK + d] : 0.f;
        qu[qi * 65 + d] = val + pu[h * DKK + d];
        qv[qi * 65 + d] = val + pv[h * DKK + d];
    }
    for (int e = tid; e < SR * DKK; e += 256) {
        int si = e >> 6, d = e & 63;
        int s = sbase + si;
        ks[si * 65 + d] = (s >= 0 && s < TT)
            ? k[((size_t)(b * TT + s)) * CC + h * DKK + d] : 0.f;
    }
    __syncthreads();

    for (int e = tid; e < TQ * NR; e += 256) {
        int qi = e & 15;
        int r  = e >> 4;
        int t = t0 + qi;
        int s = t + r - WHALF;
        float out = -1e30f;
        if (t < TT && s >= 0 && s < TT) {
            const float* pr  = pc + (size_t)r * CC + h * DKK;
            const float* quR = &qu[qi * 65];
            const float* qvR = &qv[qi * 65];
            const float* kr  = &ks[(qi + r) * 65];
            float acc = 0.f;
            #pragma unroll 8
            for (int d = 0; d < DKK; d++)
                acc += quR[d] * kr[d] + qvR[d] * pr[d];
            out = acc * 0.125f;
        }
        sc[qi * 104 + r] = out;
    }
    __syncthreads();

    for (int e = tid; e < SR * DKK; e += 256) {
        int si = e >> 6, d = e & 63;
        int s = sbase + si;
        ks[si * 65 + d] = (s >= 0 && s < TT)
            ? v[((size_t)(b * TT + s)) * CC + h * DKK + d] : 0.f;
    }
    if (tid < TQ) {
        float* srow = &sc[tid * 104];
        float m = -1e30f;
        for (int r = 0; r < NR; r++) m = fmaxf(m, srow[r]);
        float sum = 0.f;
        for (int r = 0; r < NR; r++) { float ev = __expf(srow[r] - m); srow[r] = ev; sum += ev; }
        float inv = 1.f / sum;
        for (int r = 0; r < NR; r++) srow[r] *= inv;
    }
    __syncthreads();

    for (int e = tid; e < TQ * DKK; e += 256) {
        int qi = e >> 6, d = e & 63;
        int t = t0 + qi;
        if (t < TT) {
            const float* srow = &sc[qi * 104];
            const float* vr   = &ks[qi * 65 + d];
            float acc = 0.f;
            #pragma unroll 4
            for (int r = 0; r < NR; r++) acc += srow[r] * vr[r * 65];
            o[((size_t)(b * TT + t)) * CC + h * DKK + d] = acc;
        }
    }
}

// ---------------- driver ----------------
extern "C" void kernel_launch(void* const* d_in, const int* in_sizes, int n_in,
                              void* d_out, int out_size) {
    const float* x    = (const float*)d_in[0];
    const float* Wq   = (const float*)d_in[1];
    const float* bq   = (const float*)d_in[2];
    const float* Wk   = (const float*)d_in[3];
    const float* bk   = (const float*)d_in[4];
    const float* Wv   = (const float*)d_in[5];
    const float* bv   = (const float*)d_in[6];
    const float* Wo   = (const float*)d_in[7];
    const float* bo   = (const float*)d_in[8];
    const float* Wp   = (const float*)d_in[9];
    const float* pu   = (const float*)d_in[10];
    const float* pvv  = (const float*)d_in[11];
    const float* ln1g = (const float*)d_in[12];
    const float* ln1b = (const float*)d_in[13];
    const float* ln2g = (const float*)d_in[14];
    const float* ln2b = (const float*)d_in[15];
    const float* W1   = (const float*)d_in[16];
    const float* b1   = (const float*)d_in[17];
    const float* W2   = (const float*)d_in[18];
    const float* b2   = (const float*)d_in[19];
    // d_in[20] = att_mask: fixed band |i-j|>50, handled analytically.

    float *h, *y, *q, *k, *v, *o, *pe, *pc;
    cudaGetSymbolAddress((void**)&h,  g_h);
    cudaGetSymbolAddress((void**)&y,  g_y);
    cudaGetSymbolAddress((void**)&q,  g_q);
    cudaGetSymbolAddress((void**)&k,  g_k);
    cudaGetSymbolAddress((void**)&v,  g_v);
    cudaGetSymbolAddress((void**)&o,  g_o);
    cudaGetSymbolAddress((void**)&pe, g_pe);
    cudaGetSymbolAddress((void**)&pc, g_pc);

    init_h_kernel<<<(BT*CC + 255) / 256, 256>>>(x);
    pe_kernel<<<(NR*(CC/2) + 255) / 256, 256>>>();

    dim3 gBig(CC / 64, (BT + 127) / 128);   // (12, 32)
    dim3 gQKV(3 * (CC / 64), (BT + 127) / 128);  // (36, 32)
    dim3 gP  (CC / 64, 1);                  // (12, 1), M=101
    dim3 gAtt((TT + TQ - 1) / TQ, HH, BB);  // (63, 12, 4)

    for (int l = 0; l < LNUM; l++) {
        size_t wOff = (size_t)l * CC * CC;
        size_t bOff = (size_t)l * CC;

        ln_kernel<<<BT, 256>>>(h, y, ln1g + bOff, ln1b + bOff);
        qkv_kernel<<<gQKV, 256>>>(y, Wq + wOff, Wk + wOff, Wv + wOff,
                                  bq + bOff, bk + bOff, bv + bOff, q, k, v);
        tgemm_kernel<0><<<gP, 256>>>(pe, Wp + wOff, nullptr, nullptr, pc, NR, CC, CC);
        attn_kernel<<<gAtt, 256>>>(q, k, v, pc, pu + bOff, pvv + bOff, o);
        tgemm_kernel<2><<<gBig, 256>>>(o, Wo + wOff, bo + bOff, h, h, BT, CC, CC);
        ln_kernel<<<BT, 256>>>(h, y, ln2g + bOff, ln2b + bOff);
        tgemm_kernel<1><<<gBig, 256>>>(y, W1 + wOff, b1 + bOff, nullptr, o, BT, CC, CC);
        float* outp = (l == LNUM - 1) ? (float*)d_out : h;
        tgemm_kernel<2><<<gBig, 256>>>(o, W2 + wOff, b2 + bOff, h, outp, BT, CC, CC);
    }
}

// round 7
// speedup vs baseline: 1.4801x; 1.4801x over previous
#include <cuda_runtime.h>
#include <math.h>
#include <stdint.h>

// ---------------- problem constants ----------------
#define LNUM 2
#define BB   4
#define TT   1000
#define CC   768
#define HH   12
#define DKK  64
#define WHALF 50         // band half-width (WIN//2)
#define NR   101         // relative positions actually reachable: -50..50
#define BT   (BB*TT)     // 4000 rows

// ---------------- device scratch (no allocs allowed) ----------------
__device__ float g_h[BT*CC];
__device__ float g_y[BT*CC];
__device__ float g_q[BT*CC];
__device__ float g_k[BT*CC];
__device__ float g_v[BT*CC];
__device__ float g_o[BT*CC];
__device__ float g_pe[NR*CC];   // central 101 rows of the rel-pos table
__device__ float g_pc[NR*CC];   // pe_cen @ Wp[l]

// ---------------- init: h = x * sqrt(C) ----------------
__global__ void init_h_kernel(const float* __restrict__ x) {
    int i = blockIdx.x * blockDim.x + threadIdx.x;
    if (i < BT*CC) g_h[i] = x[i] * 27.712812921102035f;  // sqrt(768)
}

// ---------------- positional table (central 101 rows only) ----------------
__global__ void pe_kernel() {
    int i = blockIdx.x * blockDim.x + threadIdx.x;
    if (i < NR*(CC/2)) {
        int r = i / (CC/2);
        int j = i % (CC/2);
        float div = expf(-(float)(2*j) * (9.210340371976184f / (float)CC)); // ln(10000)/C
        float ang = (float)(WHALF - r) * div;   // rel = -(r-50)
        g_pe[r*CC + 2*j]     = sinf(ang);
        g_pe[r*CC + 2*j + 1] = cosf(ang);
    }
}

// ---------------- LayerNorm (one block per row) ----------------
__global__ void ln_kernel(const float* __restrict__ in, float* __restrict__ out,
                          const float* __restrict__ g, const float* __restrict__ b) {
    int row = blockIdx.x;
    const float* xr = in + (size_t)row * CC;
    float s = 0.f, s2 = 0.f;
    for (int i = threadIdx.x; i < CC; i += 256) {
        float v = xr[i];
        s += v; s2 += v * v;
    }
    __shared__ float sh[16];
    #pragma unroll
    for (int o = 16; o; o >>= 1) {
        s  += __shfl_xor_sync(0xffffffffu, s,  o);
        s2 += __shfl_xor_sync(0xffffffffu, s2, o);
    }
    int w = threadIdx.x >> 5;
    if ((threadIdx.x & 31) == 0) { sh[w] = s; sh[8 + w] = s2; }
    __syncthreads();
    s = 0.f; s2 = 0.f;
    #pragma unroll
    for (int i = 0; i < 8; i++) { s += sh[i]; s2 += sh[8 + i]; }
    float mean = s * (1.f / CC);
    float var  = s2 * (1.f / CC) - mean * mean;
    float rstd = rsqrtf(var + 1e-5f);
    float* orow = out + (size_t)row * CC;
    for (int i = threadIdx.x; i < CC; i += 256)
        orow[i] = (xr[i] - mean) * rstd * g[i] + b[i];
}

// ---------------- tf32 tensor-core GEMM, cp.async staged ----------------
// C(MxN) = A(MxK) @ B(KxN) [+bias] [epilogue]. BM=128, BN=64, BK=32.
// 256 threads = 8 warps (4x2), warp tile 32x32. Double-buffered raw tiles:
//   As: m-major, row stride 36 floats  -> (36g+t) mod 32 all-distinct = CF LDS
//   Bs: k-major, row stride 68 floats  -> (68t+g) mod 32 all-distinct = CF LDS
// tf32 fed raw f32 bits (RZ). EPI: 0 none, 1 gelu, 2 +resid.

#define AST 36
#define BST 68
#define STAGE_A (128*AST)   // 4608 floats
#define STAGE_B (32*BST)    // 2176 floats
#define GEMM_SMEM ((2*STAGE_A + 2*STAGE_B) * 4)   // 54272 bytes

__device__ __forceinline__ void cp16(uint32_t dst, const void* src, int srcsize) {
    asm volatile("cp.async.cg.shared.global [%0], [%1], 16, %2;\n"
                 :: "r"(dst), "l"(src), "r"(srcsize));
}
__device__ __forceinline__ void cp_commit() {
    asm volatile("cp.async.commit_group;\n");
}
template<int N> __device__ __forceinline__ void cp_wait() {
    asm volatile("cp.async.wait_group %0;\n" :: "n"(N));
}

__device__ __forceinline__ void mma_tf32(float c[4], const uint4& a, const uint2& b) {
    asm volatile(
        "mma.sync.aligned.m16n8k8.row.col.f32.tf32.tf32.f32 "
        "{%0,%1,%2,%3}, {%4,%5,%6,%7}, {%8,%9}, {%0,%1,%2,%3};"
        : "+f"(c[0]), "+f"(c[1]), "+f"(c[2]), "+f"(c[3])
        : "r"(a.x), "r"(a.y), "r"(a.z), "r"(a.w), "r"(b.x), "r"(b.y));
}

__device__ __forceinline__ float gelu_f(float x) {
    float x3 = x * x * x;
    return 0.5f * x * (1.f + tanhf(0.7978845608028654f * (x + 0.044715f * x3)));
}

template<int EPI>
__device__ __forceinline__ void gemm_body(
        const float* __restrict__ A, const float* __restrict__ Bm,
        const float* __restrict__ bias, const float* __restrict__ resid,
        float* __restrict__ Cm, int M, int N, int K, int row0, int col0) {
    extern __shared__ float smem[];

    const int tid  = threadIdx.x;
    const int warp = tid >> 5;
    const int lane = tid & 31;
    const int g    = lane >> 2;    // 0..7
    const int t    = lane & 3;     // 0..3
    const int wr   = warp >> 1;    // 0..3 : warp row (32 M-rows)
    const int wc   = warp & 1;     // 0..1 : warp col (32 N-cols)

    float acc[2][4][4];
    #pragma unroll
    for (int i = 0; i < 2; i++)
        #pragma unroll
        for (int j = 0; j < 4; j++)
            #pragma unroll
            for (int r = 0; r < 4; r++) acc[i][j][r] = 0.f;

    // cp.async staging: A = 1024 16B chunks (8/row), B = 512 chunks (16/row)
    const int a_row = tid >> 3, a_c = tid & 7;     // + i*32 rows
    const int b_row = tid >> 4, b_c = tid & 15;    // + i*16 rows

#define LOAD_STAGE(s_) do {                                                        \
        const int p_ = (s_) & 1;                                                   \
        const int k0_ = (s_) * 32;                                                 \
        float* As_ = smem + p_ * STAGE_A;                                          \
        float* Bs_ = smem + 2 * STAGE_A + p_ * STAGE_B;                            \
        _Pragma("unroll")                                                          \
        for (int i_ = 0; i_ < 4; i_++) {                                           \
            int r_ = a_row + i_ * 32;                                              \
            int gr_ = row0 + r_;                                                   \
            int ok_ = (gr_ < M) ? 16 : 0;                                          \
            const float* src_ = A + (size_t)(ok_ ? gr_ : 0) * K + k0_ + a_c * 4;   \
            uint32_t d_ = (uint32_t)__cvta_generic_to_shared(As_ + r_ * AST + a_c * 4); \
            cp16(d_, src_, ok_);                                                   \
        }                                                                          \
        _Pragma("unroll")                                                          \
        for (int i_ = 0; i_ < 2; i_++) {                                           \
            int r_ = b_row + i_ * 16;                                              \
            const float* src_ = Bm + (size_t)(k0_ + r_) * N + col0 + b_c * 4;      \
            uint32_t d_ = (uint32_t)__cvta_generic_to_shared(Bs_ + r_ * BST + b_c * 4); \
            cp16(d_, src_, 16);                                                    \
        }                                                                          \
    } while (0)

    LOAD_STAGE(0);
    cp_commit();

    const int steps = K >> 5;   // K/32
    for (int s = 0; s < steps; s++) {
        if (s + 1 < steps) {
            LOAD_STAGE(s + 1);
            cp_commit();
            cp_wait<1>();
        } else {
            cp_wait<0>();
        }
        __syncthreads();

        const float* As = smem + (s & 1) * STAGE_A;
        const float* Bs = smem + 2 * STAGE_A + (s & 1) * STAGE_B;

        #pragma unroll
        for (int ch = 0; ch < 4; ch++) {
            uint4 af[2];
            uint2 bf[4];
            #pragma unroll
            for (int i = 0; i < 2; i++) {
                const float* ap = As + (wr * 32 + i * 16 + g) * AST + ch * 8 + t;
                af[i].x = __float_as_uint(ap[0]);
                af[i].y = __float_as_uint(ap[8 * AST]);
                af[i].z = __float_as_uint(ap[4]);
                af[i].w = __float_as_uint(ap[8 * AST + 4]);
            }
            #pragma unroll
            for (int j = 0; j < 4; j++) {
                const float* bp = Bs + (ch * 8 + t) * BST + wc * 32 + j * 8 + g;
                bf[j].x = __float_as_uint(bp[0]);
                bf[j].y = __float_as_uint(bp[4 * BST]);
            }
            #pragma unroll
            for (int i = 0; i < 2; i++)
                #pragma unroll
                for (int j = 0; j < 4; j++)
                    mma_tf32(acc[i][j], af[i], bf[j]);
        }
        __syncthreads();
    }
#undef LOAD_STAGE

    // epilogue: c0/c1 at (row g, cols 2t/2t+1), c2/c3 at row g+8
    #pragma unroll
    for (int i = 0; i < 2; i++) {
        int rbase = row0 + wr * 32 + i * 16 + g;
        #pragma unroll
        for (int j = 0; j < 4; j++) {
            int col = col0 + wc * 32 + j * 8 + t * 2;
            float bx = 0.f, by = 0.f;
            if (bias) { bx = bias[col]; by = bias[col + 1]; }
            #pragma unroll
            for (int hh = 0; hh < 2; hh++) {
                int row = rbase + hh * 8;
                if (row < M) {
                    float c0 = acc[i][j][hh * 2 + 0] + bx;
                    float c1 = acc[i][j][hh * 2 + 1] + by;
                    if (EPI == 1) { c0 = gelu_f(c0); c1 = gelu_f(c1); }
                    if (EPI == 2) {
                        float2 rv = *(const float2*)(resid + (size_t)row * N + col);
                        c0 += rv.x; c1 += rv.y;
                    }
                    *(float2*)(Cm + (size_t)row * N + col) = make_float2(c0, c1);
                }
            }
        }
    }
}

template<int EPI>
__global__ void __launch_bounds__(256)
tgemm_kernel(const float* __restrict__ A, const float* __restrict__ Bm,
             const float* __restrict__ bias, const float* __restrict__ resid,
             float* __restrict__ Cm, int M, int N, int K) {
    gemm_body<EPI>(A, Bm, bias, resid, Cm, M, N, K,
                   blockIdx.y * 128, blockIdx.x * 64);
}

// fused QKV: blockIdx.x in [0, 36); sel = x/12 picks {q,k,v}
__global__ void __launch_bounds__(256)
qkv_kernel(const float* __restrict__ A,
           const float* __restrict__ Bq, const float* __restrict__ Bk,
           const float* __restrict__ Bv,
           const float* __restrict__ bq, const float* __restrict__ bk,
           const float* __restrict__ bv,
           float* __restrict__ Cq, float* __restrict__ Ck, float* __restrict__ Cv) {
    int sel = blockIdx.x / 12;
    int colblk = blockIdx.x % 12;
    const float* Bm   = (sel == 0) ? Bq : (sel == 1) ? Bk : Bv;
    const float* bias = (sel == 0) ? bq : (sel == 1) ? bk : bv;
    float*       Cm   = (sel == 0) ? Cq : (sel == 1) ? Ck : Cv;
    gemm_body<0>(A, Bm, bias, nullptr, Cm, BT, CC, CC,
                 blockIdx.y * 128, colblk * 64);
}

// ---------------- banded rel-pos attention ----------------
#define TQ 16
#define SR (TQ + 2*WHALF)   // 116 k/v rows staged

__global__ void __launch_bounds__(256)
attn_kernel(const float* __restrict__ q, const float* __restrict__ k,
            const float* __restrict__ v, const float* __restrict__ pc,
            const float* __restrict__ pu, const float* __restrict__ pv,
            float* __restrict__ o) {
    __shared__ __align__(16) float ks[SR * 65];   // k tile, later reused for v tile
    __shared__ float qu[TQ * 65];
    __shared__ float qv[TQ * 65];
    __shared__ float sc[TQ * 104];

    int b  = blockIdx.z;
    int h  = blockIdx.y;
    int t0 = blockIdx.x * TQ;
    int sbase = t0 - WHALF;
    int tid = threadIdx.x;

    for (int e = tid; e < TQ * DKK; e += 256) {
        int qi = e >> 6, d = e & 63;
        int t = t0 + qi;
        float val = (t < TT) ? q[((size_t)(b * TT + t)) * CC + h * DKK + d] : 0.f;
        qu[qi * 65 + d] = val + pu[h * DKK + d];
        qv[qi * 65 + d] = val + pv[h * DKK + d];
    }
    for (int e = tid; e < SR * DKK; e += 256) {
        int si = e >> 6, d = e & 63;
        int s = sbase + si;
        ks[si * 65 + d] = (s >= 0 && s < TT)
            ? k[((size_t)(b * TT + s)) * CC + h * DKK + d] : 0.f;
    }
    __syncthreads();

    for (int e = tid; e < TQ * NR; e += 256) {
        int qi = e & 15;
        int r  = e >> 4;
        int t = t0 + qi;
        int s = t + r - WHALF;
        float out = -1e30f;
        if (t < TT && s >= 0 && s < TT) {
            const float* pr  = pc + (size_t)r * CC + h * DKK;
            const float* quR = &qu[qi * 65];
            const float* qvR = &qv[qi * 65];
            const float* kr  = &ks[(qi + r) * 65];
            float acc = 0.f;
            #pragma unroll 8
            for (int d = 0; d < DKK; d++)
                acc += quR[d] * kr[d] + qvR[d] * pr[d];
            out = acc * 0.125f;
        }
        sc[qi * 104 + r] = out;
    }
    __syncthreads();

    for (int e = tid; e < SR * DKK; e += 256) {
        int si = e >> 6, d = e & 63;
        int s = sbase + si;
        ks[si * 65 + d] = (s >= 0 && s < TT)
            ? v[((size_t)(b * TT + s)) * CC + h * DKK + d] : 0.f;
    }
    if (tid < TQ) {
        float* srow = &sc[tid * 104];
        float m = -1e30f;
        for (int r = 0; r < NR; r++) m = fmaxf(m, srow[r]);
        float sum = 0.f;
        for (int r = 0; r < NR; r++) { float ev = __expf(srow[r] - m); srow[r] = ev; sum += ev; }
        float inv = 1.f / sum;
        for (int r = 0; r < NR; r++) srow[r] *= inv;
    }
    __syncthreads();

    for (int e = tid; e < TQ * DKK; e += 256) {
        int qi = e >> 6, d = e & 63;
        int t = t0 + qi;
        if (t < TT) {
            const float* srow = &sc[qi * 104];
            const float* vr   = &ks[qi * 65 + d];
            float acc = 0.f;
            #pragma unroll 4
            for (int r = 0; r < NR; r++) acc += srow[r] * vr[r * 65];
            o[((size_t)(b * TT + t)) * CC + h * DKK + d] = acc;
        }
    }
}

// ---------------- driver ----------------
extern "C" void kernel_launch(void* const* d_in, const int* in_sizes, int n_in,
                              void* d_out, int out_size) {
    const float* x    = (const float*)d_in[0];
    const float* Wq   = (const float*)d_in[1];
    const float* bq   = (const float*)d_in[2];
    const float* Wk   = (const float*)d_in[3];
    const float* bk   = (const float*)d_in[4];
    const float* Wv   = (const float*)d_in[5];
    const float* bv   = (const float*)d_in[6];
    const float* Wo   = (const float*)d_in[7];
    const float* bo   = (const float*)d_in[8];
    const float* Wp   = (const float*)d_in[9];
    const float* pu   = (const float*)d_in[10];
    const float* pvv  = (const float*)d_in[11];
    const float* ln1g = (const float*)d_in[12];
    const float* ln1b = (const float*)d_in[13];
    const float* ln2g = (const float*)d_in[14];
    const float* ln2b = (const float*)d_in[15];
    const float* W1   = (const float*)d_in[16];
    const float* b1   = (const float*)d_in[17];
    const float* W2   = (const float*)d_in[18];
    const float* b2   = (const float*)d_in[19];
    // d_in[20] = att_mask: fixed band |i-j|>50, handled analytically.

    float *h, *y, *q, *k, *v, *o, *pe, *pc;
    cudaGetSymbolAddress((void**)&h,  g_h);
    cudaGetSymbolAddress((void**)&y,  g_y);
    cudaGetSymbolAddress((void**)&q,  g_q);
    cudaGetSymbolAddress((void**)&k,  g_k);
    cudaGetSymbolAddress((void**)&v,  g_v);
    cudaGetSymbolAddress((void**)&o,  g_o);
    cudaGetSymbolAddress((void**)&pe, g_pe);
    cudaGetSymbolAddress((void**)&pc, g_pc);

    cudaFuncSetAttribute(tgemm_kernel<0>, cudaFuncAttributeMaxDynamicSharedMemorySize, GEMM_SMEM);
    cudaFuncSetAttribute(tgemm_kernel<1>, cudaFuncAttributeMaxDynamicSharedMemorySize, GEMM_SMEM);
    cudaFuncSetAttribute(tgemm_kernel<2>, cudaFuncAttributeMaxDynamicSharedMemorySize, GEMM_SMEM);
    cudaFuncSetAttribute(qkv_kernel,      cudaFuncAttributeMaxDynamicSharedMemorySize, GEMM_SMEM);

    init_h_kernel<<<(BT*CC + 255) / 256, 256>>>(x);
    pe_kernel<<<(NR*(CC/2) + 255) / 256, 256>>>();

    dim3 gBig(CC / 64, (BT + 127) / 128);        // (12, 32)
    dim3 gQKV(3 * (CC / 64), (BT + 127) / 128);  // (36, 32)
    dim3 gP  (CC / 64, 1);                       // (12, 1), M=101
    dim3 gAtt((TT + TQ - 1) / TQ, HH, BB);       // (63, 12, 4)

    for (int l = 0; l < LNUM; l++) {
        size_t wOff = (size_t)l * CC * CC;
        size_t bOff = (size_t)l * CC;

        ln_kernel<<<BT, 256>>>(h, y, ln1g + bOff, ln1b + bOff);
        qkv_kernel<<<gQKV, 256, GEMM_SMEM>>>(y, Wq + wOff, Wk + wOff, Wv + wOff,
                                             bq + bOff, bk + bOff, bv + bOff, q, k, v);
        tgemm_kernel<0><<<gP, 256, GEMM_SMEM>>>(pe, Wp + wOff, nullptr, nullptr, pc, NR, CC, CC);
        attn_kernel<<<gAtt, 256>>>(q, k, v, pc, pu + bOff, pvv + bOff, o);
        tgemm_kernel<2><<<gBig, 256, GEMM_SMEM>>>(o, Wo + wOff, bo + bOff, h, h, BT, CC, CC);
        ln_kernel<<<BT, 256>>>(h, y, ln2g + bOff, ln2b + bOff);
        tgemm_kernel<1><<<gBig, 256, GEMM_SMEM>>>(y, W1 + wOff, b1 + bOff, nullptr, o, BT, CC, CC);
        float* outp = (l == LNUM - 1) ? (float*)d_out : h;
        tgemm_kernel<2><<<gBig, 256, GEMM_SMEM>>>(o, W2 + wOff, b2 + bOff, h, outp, BT, CC, CC);
    }
}

// round 8
// speedup vs baseline: 2.0397x; 1.3781x over previous
#include <cuda_runtime.h>
#include <math.h>
#include <stdint.h>

// ---------------- problem constants ----------------
#define LNUM 2
#define BB   4
#define TT   1000
#define CC   768
#define HH   12
#define DKK  64
#define WHALF 50         // band half-width (WIN//2)
#define NR   101         // relative positions actually reachable: -50..50
#define BT   (BB*TT)     // 4000 rows

// ---------------- device scratch (no allocs allowed) ----------------
__device__ float g_h[BT*CC];
__device__ float g_y[BT*CC];
__device__ float g_q[BT*CC];
__device__ float g_k[BT*CC];
__device__ float g_v[BT*CC];
__device__ float g_o[BT*CC];
__device__ float g_pe[NR*CC];   // central 101 rows of the rel-pos table
__device__ float g_pc[NR*CC];   // pe_cen @ Wp[l]

// ---------------- init: h = x * sqrt(C) ----------------
__global__ void init_h_kernel(const float* __restrict__ x) {
    int i = blockIdx.x * blockDim.x + threadIdx.x;
    if (i < BT*CC) g_h[i] = x[i] * 27.712812921102035f;  // sqrt(768)
}

// ---------------- positional table (central 101 rows only) ----------------
__global__ void pe_kernel() {
    int i = blockIdx.x * blockDim.x + threadIdx.x;
    if (i < NR*(CC/2)) {
        int r = i / (CC/2);
        int j = i % (CC/2);
        float div = expf(-(float)(2*j) * (9.210340371976184f / (float)CC)); // ln(10000)/C
        float ang = (float)(WHALF - r) * div;   // rel = -(r-50)
        g_pe[r*CC + 2*j]     = sinf(ang);
        g_pe[r*CC + 2*j + 1] = cosf(ang);
    }
}

// ---------------- LayerNorm (one block per row) ----------------
__global__ void ln_kernel(const float* __restrict__ in, float* __restrict__ out,
                          const float* __restrict__ g, const float* __restrict__ b) {
    int row = blockIdx.x;
    const float* xr = in + (size_t)row * CC;
    float s = 0.f, s2 = 0.f;
    for (int i = threadIdx.x; i < CC; i += 256) {
        float v = xr[i];
        s += v; s2 += v * v;
    }
    __shared__ float sh[16];
    #pragma unroll
    for (int o = 16; o; o >>= 1) {
        s  += __shfl_xor_sync(0xffffffffu, s,  o);
        s2 += __shfl_xor_sync(0xffffffffu, s2, o);
    }
    int w = threadIdx.x >> 5;
    if ((threadIdx.x & 31) == 0) { sh[w] = s; sh[8 + w] = s2; }
    __syncthreads();
    s = 0.f; s2 = 0.f;
    #pragma unroll
    for (int i = 0; i < 8; i++) { s += sh[i]; s2 += sh[8 + i]; }
    float mean = s * (1.f / CC);
    float var  = s2 * (1.f / CC) - mean * mean;
    float rstd = rsqrtf(var + 1e-5f);
    float* orow = out + (size_t)row * CC;
    for (int i = threadIdx.x; i < CC; i += 256)
        orow[i] = (xr[i] - mean) * rstd * g[i] + b[i];
}

// ---------------- tf32 mma helper ----------------
__device__ __forceinline__ void mma_tf32(float c[4], const uint4& a, const uint2& b) {
    asm volatile(
        "mma.sync.aligned.m16n8k8.row.col.f32.tf32.tf32.f32 "
        "{%0,%1,%2,%3}, {%4,%5,%6,%7}, {%8,%9}, {%0,%1,%2,%3};"
        : "+f"(c[0]), "+f"(c[1]), "+f"(c[2]), "+f"(c[3])
        : "r"(a.x), "r"(a.y), "r"(a.z), "r"(a.w), "r"(b.x), "r"(b.y));
}

// ---------------- tf32 tensor-core GEMM, cp.async staged ----------------
#define AST 36
#define BST 68
#define STAGE_A (128*AST)   // 4608 floats
#define STAGE_B (32*BST)    // 2176 floats
#define GEMM_SMEM ((2*STAGE_A + 2*STAGE_B) * 4)   // 54272 bytes

__device__ __forceinline__ void cp16(uint32_t dst, const void* src, int srcsize) {
    asm volatile("cp.async.cg.shared.global [%0], [%1], 16, %2;\n"
                 :: "r"(dst), "l"(src), "r"(srcsize));
}
__device__ __forceinline__ void cp_commit() {
    asm volatile("cp.async.commit_group;\n");
}
template<int N> __device__ __forceinline__ void cp_wait() {
    asm volatile("cp.async.wait_group %0;\n" :: "n"(N));
}

__device__ __forceinline__ float gelu_f(float x) {
    float x3 = x * x * x;
    return 0.5f * x * (1.f + tanhf(0.7978845608028654f * (x + 0.044715f * x3)));
}

template<int EPI>
__device__ __forceinline__ void gemm_body(
        const float* __restrict__ A, const float* __restrict__ Bm,
        const float* __restrict__ bias, const float* __restrict__ resid,
        float* __restrict__ Cm, int M, int N, int K, int row0, int col0) {
    extern __shared__ float smem[];

    const int tid  = threadIdx.x;
    const int warp = tid >> 5;
    const int lane = tid & 31;
    const int g    = lane >> 2;    // 0..7
    const int t    = lane & 3;     // 0..3
    const int wr   = warp >> 1;    // 0..3 : warp row (32 M-rows)
    const int wc   = warp & 1;     // 0..1 : warp col (32 N-cols)

    float acc[2][4][4];
    #pragma unroll
    for (int i = 0; i < 2; i++)
        #pragma unroll
        for (int j = 0; j < 4; j++)
            #pragma unroll
            for (int r = 0; r < 4; r++) acc[i][j][r] = 0.f;

    const int a_row = tid >> 3, a_c = tid & 7;     // + i*32 rows
    const int b_row = tid >> 4, b_c = tid & 15;    // + i*16 rows

#define LOAD_STAGE(s_) do {                                                        \
        const int p_ = (s_) & 1;                                                   \
        const int k0_ = (s_) * 32;                                                 \
        float* As_ = smem + p_ * STAGE_A;                                          \
        float* Bs_ = smem + 2 * STAGE_A + p_ * STAGE_B;                            \
        _Pragma("unroll")                                                          \
        for (int i_ = 0; i_ < 4; i_++) {                                           \
            int r_ = a_row + i_ * 32;                                              \
            int gr_ = row0 + r_;                                                   \
            int ok_ = (gr_ < M) ? 16 : 0;                                          \
            const float* src_ = A + (size_t)(ok_ ? gr_ : 0) * K + k0_ + a_c * 4;   \
            uint32_t d_ = (uint32_t)__cvta_generic_to_shared(As_ + r_ * AST + a_c * 4); \
            cp16(d_, src_, ok_);                                                   \
        }                                                                          \
        _Pragma("unroll")                                                          \
        for (int i_ = 0; i_ < 2; i_++) {                                           \
            int r_ = b_row + i_ * 16;                                              \
            const float* src_ = Bm + (size_t)(k0_ + r_) * N + col0 + b_c * 4;      \
            uint32_t d_ = (uint32_t)__cvta_generic_to_shared(Bs_ + r_ * BST + b_c * 4); \
            cp16(d_, src_, 16);                                                    \
        }                                                                          \
    } while (0)

    LOAD_STAGE(0);
    cp_commit();

    const int steps = K >> 5;   // K/32
    for (int s = 0; s < steps; s++) {
        if (s + 1 < steps) {
            LOAD_STAGE(s + 1);
            cp_commit();
            cp_wait<1>();
        } else {
            cp_wait<0>();
        }
        __syncthreads();

        const float* As = smem + (s & 1) * STAGE_A;
        const float* Bs = smem + 2 * STAGE_A + (s & 1) * STAGE_B;

        #pragma unroll
        for (int ch = 0; ch < 4; ch++) {
            uint4 af[2];
            uint2 bf[4];
            #pragma unroll
            for (int i = 0; i < 2; i++) {
                const float* ap = As + (wr * 32 + i * 16 + g) * AST + ch * 8 + t;
                af[i].x = __float_as_uint(ap[0]);
                af[i].y = __float_as_uint(ap[8 * AST]);
                af[i].z = __float_as_uint(ap[4]);
                af[i].w = __float_as_uint(ap[8 * AST + 4]);
            }
            #pragma unroll
            for (int j = 0; j < 4; j++) {
                const float* bp = Bs + (ch * 8 + t) * BST + wc * 32 + j * 8 + g;
                bf[j].x = __float_as_uint(bp[0]);
                bf[j].y = __float_as_uint(bp[4 * BST]);
            }
            #pragma unroll
            for (int i = 0; i < 2; i++)
                #pragma unroll
                for (int j = 0; j < 4; j++)
                    mma_tf32(acc[i][j], af[i], bf[j]);
        }
        __syncthreads();
    }
#undef LOAD_STAGE

    #pragma unroll
    for (int i = 0; i < 2; i++) {
        int rbase = row0 + wr * 32 + i * 16 + g;
        #pragma unroll
        for (int j = 0; j < 4; j++) {
            int col = col0 + wc * 32 + j * 8 + t * 2;
            float bx = 0.f, by = 0.f;
            if (bias) { bx = bias[col]; by = bias[col + 1]; }
            #pragma unroll
            for (int hh = 0; hh < 2; hh++) {
                int row = rbase + hh * 8;
                if (row < M) {
                    float c0 = acc[i][j][hh * 2 + 0] + bx;
                    float c1 = acc[i][j][hh * 2 + 1] + by;
                    if (EPI == 1) { c0 = gelu_f(c0); c1 = gelu_f(c1); }
                    if (EPI == 2) {
                        float2 rv = *(const float2*)(resid + (size_t)row * N + col);
                        c0 += rv.x; c1 += rv.y;
                    }
                    *(float2*)(Cm + (size_t)row * N + col) = make_float2(c0, c1);
                }
            }
        }
    }
}

template<int EPI>
__global__ void __launch_bounds__(256)
tgemm_kernel(const float* __restrict__ A, const float* __restrict__ Bm,
             const float* __restrict__ bias, const float* __restrict__ resid,
             float* __restrict__ Cm, int M, int N, int K) {
    gemm_body<EPI>(A, Bm, bias, resid, Cm, M, N, K,
                   blockIdx.y * 128, blockIdx.x * 64);
}

__global__ void __launch_bounds__(256)
qkv_kernel(const float* __restrict__ A,
           const float* __restrict__ Bq, const float* __restrict__ Bk,
           const float* __restrict__ Bv,
           const float* __restrict__ bq, const float* __restrict__ bk,
           const float* __restrict__ bv,
           float* __restrict__ Cq, float* __restrict__ Ck, float* __restrict__ Cv) {
    int sel = blockIdx.x / 12;
    int colblk = blockIdx.x % 12;
    const float* Bm   = (sel == 0) ? Bq : (sel == 1) ? Bk : Bv;
    const float* bias = (sel == 0) ? bq : (sel == 1) ? bk : bv;
    float*       Cm   = (sel == 0) ? Cq : (sel == 1) ? Ck : Cv;
    gemm_body<0>(A, Bm, bias, nullptr, Cm, BT, CC, CC,
                 blockIdx.y * 128, colblk * 64);
}

// ---------------- banded rel-pos attention (tensor-core) ----------------
// Per block: (b, h, 16 queries). All dots via tf32 mma m16n8k8.
//  GEMM1: S1'[16][120] = QU(16x64) @ Kst^T        (si = staged index; S[qi][r]=S1'[qi][qi+r])
//  GEMM2: S2'[16][104] = QV(16x64) @ Pst^T
//  combine + mask -> softmax -> scatter into shifted attn'[16][120]
//  GEMM3: O[16][64]   = attn'(16x120) @ Vst(120x64)
// Smem strides chosen for conflict-free fragment LDS:
//  QU/QV/Kst/Pst stride 68 (bank 4g+t), Vst stride 72 (8t+g), attn' stride 132 (4g+t).
#define TQ 16
#define SRR 120          // staged k/v rows (116 used, padded to 120 for k-tiling)

#define OF_KV 0
#define KVST  72
#define KST   68
#define OF_QU 8640
#define QST   68
#define OF_QV 9728
#define OF_PS 10816
#define PST   68
#define OF_S1 17888
#define S1ST  132
#define OF_SC 20000
#define SCST  104
#define ATTN_SMEM_BYTES (21664 * 4)

__global__ void __launch_bounds__(256)
attn_kernel(const float* __restrict__ q, const float* __restrict__ k,
            const float* __restrict__ v, const float* __restrict__ pc,
            const float* __restrict__ pu, const float* __restrict__ pv,
            float* __restrict__ o) {
    extern __shared__ float sm[];
    float* KV = sm + OF_KV;
    float* QU = sm + OF_QU;
    float* QV = sm + OF_QV;
    float* PS = sm + OF_PS;
    float* S1 = sm + OF_S1;
    float* SC = sm + OF_SC;

    const int b  = blockIdx.z;
    const int h  = blockIdx.y;
    const int t0 = blockIdx.x * TQ;
    const int sbase = t0 - WHALF;
    const int tid = threadIdx.x;
    const int warp = tid >> 5, lane = tid & 31;
    const int g = lane >> 2, t4 = lane & 3;

    // ---- phase 1: stage QU/QV (16x64), Kst (120x64), Pst (104x64)
    for (int e = tid; e < TQ * 16; e += 256) {
        int qi = e >> 4, d4 = (e & 15) * 4;
        int tt = t0 + qi;
        float4 qq = make_float4(0.f, 0.f, 0.f, 0.f);
        if (tt < TT) qq = *(const float4*)(q + ((size_t)(b*TT+tt))*CC + h*DKK + d4);
        float4 u4 = *(const float4*)(pu + h*DKK + d4);
        float4 v4 = *(const float4*)(pv + h*DKK + d4);
        *(float4*)(QU + qi*QST + d4) = make_float4(qq.x+u4.x, qq.y+u4.y, qq.z+u4.z, qq.w+u4.w);
        *(float4*)(QV + qi*QST + d4) = make_float4(qq.x+v4.x, qq.y+v4.y, qq.z+v4.z, qq.w+v4.w);
    }
    for (int e = tid; e < SRR * 16; e += 256) {
        int si = e >> 4, d4 = (e & 15) * 4;
        int s = sbase + si;
        float4 kk = make_float4(0.f, 0.f, 0.f, 0.f);
        if (s >= 0 && s < TT) kk = *(const float4*)(k + ((size_t)(b*TT+s))*CC + h*DKK + d4);
        *(float4*)(KV + si*KST + d4) = kk;
    }
    for (int e = tid; e < 104 * 16; e += 256) {
        int r = e >> 4, d4 = (e & 15) * 4;
        float4 pp = make_float4(0.f, 0.f, 0.f, 0.f);
        if (r < NR) pp = *(const float4*)(pc + (size_t)r*CC + h*DKK + d4);
        *(float4*)(PS + r*PST + d4) = pp;
    }
    __syncthreads();

    // ---- phase 2: GEMM1 (QU @ Kst^T -> S1', stride 132) and GEMM2 (QV @ Pst^T -> SC)
    for (int nt = warp; nt < 15; nt += 8) {
        float c[4] = {0.f, 0.f, 0.f, 0.f};
        #pragma unroll
        for (int ch = 0; ch < 8; ch++) {
            uint4 a;
            a.x = __float_as_uint(QU[g*QST + ch*8 + t4]);
            a.y = __float_as_uint(QU[(g+8)*QST + ch*8 + t4]);
            a.z = __float_as_uint(QU[g*QST + ch*8 + t4 + 4]);
            a.w = __float_as_uint(QU[(g+8)*QST + ch*8 + t4 + 4]);
            uint2 bq;
            bq.x = __float_as_uint(KV[(nt*8+g)*KST + ch*8 + t4]);
            bq.y = __float_as_uint(KV[(nt*8+g)*KST + ch*8 + t4 + 4]);
            mma_tf32(c, a, bq);
        }
        *(float2*)(S1 + g*S1ST + nt*8 + 2*t4)       = make_float2(c[0], c[1]);
        *(float2*)(S1 + (g+8)*S1ST + nt*8 + 2*t4)   = make_float2(c[2], c[3]);
    }
    for (int nt = warp; nt < 13; nt += 8) {
        float c[4] = {0.f, 0.f, 0.f, 0.f};
        #pragma unroll
        for (int ch = 0; ch < 8; ch++) {
            uint4 a;
            a.x = __float_as_uint(QV[g*QST + ch*8 + t4]);
            a.y = __float_as_uint(QV[(g+8)*QST + ch*8 + t4]);
            a.z = __float_as_uint(QV[g*QST + ch*8 + t4 + 4]);
            a.w = __float_as_uint(QV[(g+8)*QST + ch*8 + t4 + 4]);
            uint2 bq;
            bq.x = __float_as_uint(PS[(nt*8+g)*PST + ch*8 + t4]);
            bq.y = __float_as_uint(PS[(nt*8+g)*PST + ch*8 + t4 + 4]);
            mma_tf32(c, a, bq);
        }
        *(float2*)(SC + g*SCST + nt*8 + 2*t4)       = make_float2(c[0], c[1]);
        *(float2*)(SC + (g+8)*SCST + nt*8 + 2*t4)   = make_float2(c[2], c[3]);
    }
    __syncthreads();

    // ---- phase 3a: combine + mask -> SC ; stage V into KV (stride 72)
    for (int e = tid; e < TQ * NR; e += 256) {
        int qi = e & 15, r = e >> 4;
        int tt = t0 + qi, s = tt + r - WHALF;
        float val = -1e30f;
        if (tt < TT && s >= 0 && s < TT)
            val = (S1[qi*S1ST + qi + r] + SC[qi*SCST + r]) * 0.125f;
        SC[qi*SCST + r] = val;
    }
    for (int e = tid; e < SRR * 16; e += 256) {
        int si = e >> 4, d4 = (e & 15) * 4;
        int s = sbase + si;
        float4 vv = make_float4(0.f, 0.f, 0.f, 0.f);
        if (s >= 0 && s < TT) vv = *(const float4*)(v + ((size_t)(b*TT+s))*CC + h*DKK + d4);
        *(float4*)(KV + si*KVST + d4) = vv;
    }
    __syncthreads();

    // ---- phase 3b: zero attn' (S1 buffer) ; softmax rows of SC
    for (int e = tid; e < TQ * S1ST; e += 256) S1[e] = 0.f;
    if (tid < TQ) {
        float* srow = SC + tid * SCST;
        float m = -1e30f;
        for (int r = 0; r < NR; r++) m = fmaxf(m, srow[r]);
        float sum = 0.f;
        for (int r = 0; r < NR; r++) { float ev = __expf(srow[r] - m); srow[r] = ev; sum += ev; }
        float inv = 1.f / sum;
        for (int r = 0; r < NR; r++) srow[r] *= inv;
    }
    __syncthreads();

    // ---- phase 3c: scatter shifted attention weights into attn'
    for (int e = tid; e < TQ * NR; e += 256) {
        int qi = e & 15, r = e >> 4;
        S1[qi*S1ST + qi + r] = SC[qi*SCST + r];
    }
    __syncthreads();

    // ---- phase 4: GEMM3  O = attn'(16x120) @ Vst(120x64), one n8-tile per warp
    {
        int n0 = warp * 8;
        float c[4] = {0.f, 0.f, 0.f, 0.f};
        #pragma unroll
        for (int ch = 0; ch < 15; ch++) {
            uint4 a;
            a.x = __float_as_uint(S1[g*S1ST + ch*8 + t4]);
            a.y = __float_as_uint(S1[(g+8)*S1ST + ch*8 + t4]);
            a.z = __float_as_uint(S1[g*S1ST + ch*8 + t4 + 4]);
            a.w = __float_as_uint(S1[(g+8)*S1ST + ch*8 + t4 + 4]);
            uint2 bq;
            bq.x = __float_as_uint(KV[(ch*8+t4)*KVST + n0 + g]);
            bq.y = __float_as_uint(KV[(ch*8+t4+4)*KVST + n0 + g]);
            mma_tf32(c, a, bq);
        }
        int tg0 = t0 + g, tg1 = t0 + g + 8;
        if (tg0 < TT)
            *(float2*)(o + ((size_t)(b*TT+tg0))*CC + h*DKK + n0 + 2*t4) = make_float2(c[0], c[1]);
        if (tg1 < TT)
            *(float2*)(o + ((size_t)(b*TT+tg1))*CC + h*DKK + n0 + 2*t4) = make_float2(c[2], c[3]);
    }
}

// ---------------- driver ----------------
extern "C" void kernel_launch(void* const* d_in, const int* in_sizes, int n_in,
                              void* d_out, int out_size) {
    const float* x    = (const float*)d_in[0];
    const float* Wq   = (const float*)d_in[1];
    const float* bq   = (const float*)d_in[2];
    const float* Wk   = (const float*)d_in[3];
    const float* bk   = (const float*)d_in[4];
    const float* Wv   = (const float*)d_in[5];
    const float* bv   = (const float*)d_in[6];
    const float* Wo   = (const float*)d_in[7];
    const float* bo   = (const float*)d_in[8];
    const float* Wp   = (const float*)d_in[9];
    const float* pu   = (const float*)d_in[10];
    const float* pvv  = (const float*)d_in[11];
    const float* ln1g = (const float*)d_in[12];
    const float* ln1b = (const float*)d_in[13];
    const float* ln2g = (const float*)d_in[14];
    const float* ln2b = (const float*)d_in[15];
    const float* W1   = (const float*)d_in[16];
    const float* b1   = (const float*)d_in[17];
    const float* W2   = (const float*)d_in[18];
    const float* b2   = (const float*)d_in[19];
    // d_in[20] = att_mask: fixed band |i-j|>50, handled analytically.

    float *h, *y, *q, *k, *v, *o, *pe, *pc;
    cudaGetSymbolAddress((void**)&h,  g_h);
    cudaGetSymbolAddress((void**)&y,  g_y);
    cudaGetSymbolAddress((void**)&q,  g_q);
    cudaGetSymbolAddress((void**)&k,  g_k);
    cudaGetSymbolAddress((void**)&v,  g_v);
    cudaGetSymbolAddress((void**)&o,  g_o);
    cudaGetSymbolAddress((void**)&pe, g_pe);
    cudaGetSymbolAddress((void**)&pc, g_pc);

    cudaFuncSetAttribute(tgemm_kernel<0>, cudaFuncAttributeMaxDynamicSharedMemorySize, GEMM_SMEM);
    cudaFuncSetAttribute(tgemm_kernel<1>, cudaFuncAttributeMaxDynamicSharedMemorySize, GEMM_SMEM);
    cudaFuncSetAttribute(tgemm_kernel<2>, cudaFuncAttributeMaxDynamicSharedMemorySize, GEMM_SMEM);
    cudaFuncSetAttribute(qkv_kernel,      cudaFuncAttributeMaxDynamicSharedMemorySize, GEMM_SMEM);
    cudaFuncSetAttribute(attn_kernel,     cudaFuncAttributeMaxDynamicSharedMemorySize, ATTN_SMEM_BYTES);

    init_h_kernel<<<(BT*CC + 255) / 256, 256>>>(x);
    pe_kernel<<<(NR*(CC/2) + 255) / 256, 256>>>();

    dim3 gBig(CC / 64, (BT + 127) / 128);        // (12, 32)
    dim3 gQKV(3 * (CC / 64), (BT + 127) / 128);  // (36, 32)
    dim3 gP  (CC / 64, 1);                       // (12, 1), M=101
    dim3 gAtt((TT + TQ - 1) / TQ, HH, BB);       // (63, 12, 4)

    for (int l = 0; l < LNUM; l++) {
        size_t wOff = (size_t)l * CC * CC;
        size_t bOff = (size_t)l * CC;

        ln_kernel<<<BT, 256>>>(h, y, ln1g + bOff, ln1b + bOff);
        qkv_kernel<<<gQKV, 256, GEMM_SMEM>>>(y, Wq + wOff, Wk + wOff, Wv + wOff,
                                             bq + bOff, bk + bOff, bv + bOff, q, k, v);
        tgemm_kernel<0><<<gP, 256, GEMM_SMEM>>>(pe, Wp + wOff, nullptr, nullptr, pc, NR, CC, CC);
        attn_kernel<<<gAtt, 256, ATTN_SMEM_BYTES>>>(q, k, v, pc, pu + bOff, pvv + bOff, o);
        tgemm_kernel<2><<<gBig, 256, GEMM_SMEM>>>(o, Wo + wOff, bo + bOff, h, h, BT, CC, CC);
        ln_kernel<<<BT, 256>>>(h, y, ln2g + bOff, ln2b + bOff);
        tgemm_kernel<1><<<gBig, 256, GEMM_SMEM>>>(y, W1 + wOff, b1 + bOff, nullptr, o, BT, CC, CC);
        float* outp = (l == LNUM - 1) ? (float*)d_out : h;
        tgemm_kernel<2><<<gBig, 256, GEMM_SMEM>>>(o, W2 + wOff, b2 + bOff, h, outp, BT, CC, CC);
    }
}

// round 9
// speedup vs baseline: 2.9337x; 1.4382x over previous
#include <cuda_runtime.h>
#include <cuda_bf16.h>
#include <math.h>
#include <stdint.h>

// ---------------- problem constants ----------------
#define LNUM 2
#define BB   4
#define TT   1000
#define CC   768
#define HH   12
#define DKK  64
#define WHALF 50         // band half-width (WIN//2)
#define NR   101         // relative positions actually reachable: -50..50
#define BT   (BB*TT)     // 4000 rows

// ---------------- device scratch (no allocs allowed) ----------------
__device__ float g_h[BT*CC];
__device__ float g_q[BT*CC];
__device__ float g_k[BT*CC];
__device__ float g_v[BT*CC];
__device__ float g_pc[NR*CC];                 // pe @ Wp[l]  (fp32, attention input)
__device__ __nv_bfloat16 g_ybf[BT*CC];        // LN output (GEMM A operand)
__device__ __nv_bfloat16 g_obf[BT*CC];        // attn out / gelu out (GEMM A operand)
__device__ __nv_bfloat16 g_pebf[NR*CC];       // positional table, bf16
__device__ __nv_bfloat16 g_wbf[7*LNUM*CC*CC]; // bf16 weights: Wq,Wk,Wv,Wo,Wp,W1,W2

// ---------------- small kernels ----------------
__global__ void init_h_kernel(const float* __restrict__ x) {
    int i = blockIdx.x * blockDim.x + threadIdx.x;
    if (i < BT*CC) g_h[i] = x[i] * 27.712812921102035f;  // sqrt(768)
}

__global__ void f2b_kernel(const float* __restrict__ src, __nv_bfloat16* __restrict__ dst, int n) {
    int i = blockIdx.x * blockDim.x + threadIdx.x;
    if (i < n) dst[i] = __float2bfloat16(src[i]);
}

__global__ void pe_kernel() {
    int i = blockIdx.x * blockDim.x + threadIdx.x;
    if (i < NR*(CC/2)) {
        int r = i / (CC/2);
        int j = i % (CC/2);
        float div = expf(-(float)(2*j) * (9.210340371976184f / (float)CC)); // ln(10000)/C
        float ang = (float)(WHALF - r) * div;   // rel = -(r-50)
        g_pebf[r*CC + 2*j]     = __float2bfloat16(sinf(ang));
        g_pebf[r*CC + 2*j + 1] = __float2bfloat16(cosf(ang));
    }
}

// LayerNorm: fp32 in, bf16 out
__global__ void ln_kernel(const float* __restrict__ in, __nv_bfloat16* __restrict__ out,
                          const float* __restrict__ g, const float* __restrict__ b) {
    int row = blockIdx.x;
    const float* xr = in + (size_t)row * CC;
    float s = 0.f, s2 = 0.f;
    for (int i = threadIdx.x; i < CC; i += 256) {
        float v = xr[i];
        s += v; s2 += v * v;
    }
    __shared__ float sh[16];
    #pragma unroll
    for (int o = 16; o; o >>= 1) {
        s  += __shfl_xor_sync(0xffffffffu, s,  o);
        s2 += __shfl_xor_sync(0xffffffffu, s2, o);
    }
    int w = threadIdx.x >> 5;
    if ((threadIdx.x & 31) == 0) { sh[w] = s; sh[8 + w] = s2; }
    __syncthreads();
    s = 0.f; s2 = 0.f;
    #pragma unroll
    for (int i = 0; i < 8; i++) { s += sh[i]; s2 += sh[8 + i]; }
    float mean = s * (1.f / CC);
    float var  = s2 * (1.f / CC) - mean * mean;
    float rstd = rsqrtf(var + 1e-5f);
    __nv_bfloat16* orow = out + (size_t)row * CC;
    for (int i = threadIdx.x; i < CC; i += 256)
        orow[i] = __float2bfloat16((xr[i] - mean) * rstd * g[i] + b[i]);
}

// ---------------- mma / ldmatrix / cp.async helpers ----------------
__device__ __forceinline__ void mma_tf32(float c[4], const uint4& a, const uint2& b) {
    asm volatile(
        "mma.sync.aligned.m16n8k8.row.col.f32.tf32.tf32.f32 "
        "{%0,%1,%2,%3}, {%4,%5,%6,%7}, {%8,%9}, {%0,%1,%2,%3};"
        : "+f"(c[0]), "+f"(c[1]), "+f"(c[2]), "+f"(c[3])
        : "r"(a.x), "r"(a.y), "r"(a.z), "r"(a.w), "r"(b.x), "r"(b.y));
}
__device__ __forceinline__ void mma_bf16(float c[4], const uint4& a, uint32_t b0, uint32_t b1) {
    asm volatile(
        "mma.sync.aligned.m16n8k16.row.col.f32.bf16.bf16.f32 "
        "{%0,%1,%2,%3}, {%4,%5,%6,%7}, {%8,%9}, {%0,%1,%2,%3};"
        : "+f"(c[0]), "+f"(c[1]), "+f"(c[2]), "+f"(c[3])
        : "r"(a.x), "r"(a.y), "r"(a.z), "r"(a.w), "r"(b0), "r"(b1));
}
__device__ __forceinline__ void ldsm_x4(uint4& d, uint32_t addr) {
    asm volatile("ldmatrix.sync.aligned.m8n8.x4.shared.b16 {%0,%1,%2,%3}, [%4];"
                 : "=r"(d.x), "=r"(d.y), "=r"(d.z), "=r"(d.w) : "r"(addr));
}
__device__ __forceinline__ void ldsm_x4_t(uint4& d, uint32_t addr) {
    asm volatile("ldmatrix.sync.aligned.m8n8.x4.trans.shared.b16 {%0,%1,%2,%3}, [%4];"
                 : "=r"(d.x), "=r"(d.y), "=r"(d.z), "=r"(d.w) : "r"(addr));
}
__device__ __forceinline__ void cp16(uint32_t dst, const void* src, int srcsize) {
    asm volatile("cp.async.cg.shared.global [%0], [%1], 16, %2;\n"
                 :: "r"(dst), "l"(src), "r"(srcsize));
}
__device__ __forceinline__ void cp_commit() {
    asm volatile("cp.async.commit_group;\n");
}
template<int N> __device__ __forceinline__ void cp_wait() {
    asm volatile("cp.async.wait_group %0;\n" :: "n"(N));
}

__device__ __forceinline__ float gelu_f(float x) {
    float x3 = x * x * x;
    return 0.5f * x * (1.f + tanhf(0.7978845608028654f * (x + 0.044715f * x3)));
}

// ---------------- bf16 tensor-core GEMM, 3-stage cp.async ----------------
// C(MxN) = A(MxK) @ B(KxN) [+bias] [epilogue]. BM=128, BN=64, BK=32 (bf16).
// 256 threads = 8 warps (4 row x 2 col), warp tile 32x32.
// A staged m-major, row stride 20 u32 (32 bf16 + pad) -> CF ldmatrix.
// B staged k-major, row stride 36 u32 (64 bf16 + pad)  -> CF ldmatrix.trans.
// EPI: 0 none, 1 gelu, 2 +resid.  OUTBF: 1 -> write bf16 C, else fp32.
#define AST2 20
#define BST2 36
#define STG_A (128*AST2)   // 2560 u32
#define STG_B (32*BST2)    // 1152 u32
#define GEMM_SMEM (3*(STG_A+STG_B)*4)   // 44544 bytes

template<int EPI, int OUTBF>
__device__ __forceinline__ void gemm_body(
        const __nv_bfloat16* __restrict__ A, const __nv_bfloat16* __restrict__ Bm,
        const float* __restrict__ bias, const float* __restrict__ resid,
        void* __restrict__ Cm, int M, int N, int K, int row0, int col0) {
    extern __shared__ uint32_t smu[];
    const uint32_t smem_base = (uint32_t)__cvta_generic_to_shared(smu);

    const int tid  = threadIdx.x;
    const int warp = tid >> 5;
    const int lane = tid & 31;
    const int g    = lane >> 2;
    const int t    = lane & 3;
    const int wr   = warp >> 1;    // 0..3 : 32 M-rows
    const int wc   = warp & 1;     // 0..1 : 32 N-cols

    float acc[2][4][4];
    #pragma unroll
    for (int i = 0; i < 2; i++)
        #pragma unroll
        for (int j = 0; j < 4; j++)
            #pragma unroll
            for (int r = 0; r < 4; r++) acc[i][j][r] = 0.f;

    const int a_r = tid >> 2, a_c = tid & 3;    // A rows a_r, a_r+64; 4 chunks/row
    const int b_r = tid >> 3, b_c = tid & 7;    // B 32 rows x 8 chunks

#define LOADS(s_) do {                                                              \
        const int k0_ = (s_) * 32;                                                  \
        uint32_t* Ab_ = smu + ((s_) % 3) * (STG_A + STG_B);                         \
        uint32_t* Bb_ = Ab_ + STG_A;                                                \
        _Pragma("unroll")                                                           \
        for (int i_ = 0; i_ < 2; i_++) {                                            \
            int r_ = a_r + i_ * 64;                                                 \
            int gr_ = row0 + r_;                                                    \
            int ok_ = (gr_ < M) ? 16 : 0;                                           \
            const __nv_bfloat16* src_ = A + (size_t)(ok_ ? gr_ : 0) * K + k0_ + a_c * 8; \
            cp16((uint32_t)__cvta_generic_to_shared(Ab_ + r_ * AST2 + a_c * 4), src_, ok_); \
        }                                                                           \
        {                                                                           \
            const __nv_bfloat16* src_ = Bm + (size_t)(k0_ + b_r) * N + col0 + b_c * 8;   \
            cp16((uint32_t)__cvta_generic_to_shared(Bb_ + b_r * BST2 + b_c * 4), src_, 16); \
        }                                                                           \
    } while (0)

    const int steps = K >> 5;   // K/32
    LOADS(0); cp_commit();
    LOADS(1); cp_commit();

    // per-lane ldmatrix address components (u32 units, converted to bytes below)
    const int a_lane_off = (lane & 15) * AST2 + (lane >> 4) * 4;
    const int b_lane_off = (lane & 15) * BST2 + wc * 16 + (lane >> 4) * 4;

    for (int s = 0; s < steps; s++) {
        cp_wait<1>();
        __syncthreads();
        if (s + 2 < steps) LOADS(s + 2);
        cp_commit();

        const uint32_t bufo = (uint32_t)((s % 3) * (STG_A + STG_B));
        const uint32_t abase = smem_base + (bufo + wr * 32 * AST2 + a_lane_off) * 4;
        const uint32_t bbase = smem_base + (bufo + STG_A + b_lane_off) * 4;

        #pragma unroll
        for (int ch = 0; ch < 2; ch++) {       // two k16 chunks of BK=32
            uint4 af[2];
            #pragma unroll
            for (int i = 0; i < 2; i++)
                ldsm_x4(af[i], abase + (i * 16 * AST2 + ch * 8) * 4);
            uint4 bq[2];
            #pragma unroll
            for (int jj = 0; jj < 2; jj++)
                ldsm_x4_t(bq[jj], bbase + (ch * 16 * BST2 + jj * 8) * 4);
            #pragma unroll
            for (int i = 0; i < 2; i++) {
                mma_bf16(acc[i][0], af[i], bq[0].x, bq[0].y);
                mma_bf16(acc[i][1], af[i], bq[0].z, bq[0].w);
                mma_bf16(acc[i][2], af[i], bq[1].x, bq[1].y);
                mma_bf16(acc[i][3], af[i], bq[1].z, bq[1].w);
            }
        }
    }
#undef LOADS

    __syncthreads();  // before any next-kernel reuse; also separates epilogue

    #pragma unroll
    for (int i = 0; i < 2; i++) {
        int rbase = row0 + wr * 32 + i * 16 + g;
        #pragma unroll
        for (int j = 0; j < 4; j++) {
            int col = col0 + wc * 32 + j * 8 + t * 2;
            float bx = 0.f, by = 0.f;
            if (bias) { bx = bias[col]; by = bias[col + 1]; }
            #pragma unroll
            for (int hh = 0; hh < 2; hh++) {
                int row = rbase + hh * 8;
                if (row < M) {
                    float c0 = acc[i][j][hh * 2 + 0] + bx;
                    float c1 = acc[i][j][hh * 2 + 1] + by;
                    if (EPI == 1) { c0 = gelu_f(c0); c1 = gelu_f(c1); }
                    if (EPI == 2) {
                        float2 rv = *(const float2*)(resid + (size_t)row * N + col);
                        c0 += rv.x; c1 += rv.y;
                    }
                    if (OUTBF) {
                        __nv_bfloat162 p;
                        p.x = __float2bfloat16(c0);
                        p.y = __float2bfloat16(c1);
                        *(__nv_bfloat162*)((__nv_bfloat16*)Cm + (size_t)row * N + col) = p;
                    } else {
                        *(float2*)((float*)Cm + (size_t)row * N + col) = make_float2(c0, c1);
                    }
                }
            }
        }
    }
}

template<int EPI, int OUTBF>
__global__ void __launch_bounds__(256)
tgemm_kernel(const __nv_bfloat16* __restrict__ A, const __nv_bfloat16* __restrict__ Bm,
             const float* __restrict__ bias, const float* __restrict__ resid,
             void* __restrict__ Cm, int M, int N, int K) {
    gemm_body<EPI, OUTBF>(A, Bm, bias, resid, Cm, M, N, K,
                          blockIdx.y * 128, blockIdx.x * 64);
}

__global__ void __launch_bounds__(256)
qkv_kernel(const __nv_bfloat16* __restrict__ A,
           const __nv_bfloat16* __restrict__ Bq, const __nv_bfloat16* __restrict__ Bk,
           const __nv_bfloat16* __restrict__ Bv,
           const float* __restrict__ bq, const float* __restrict__ bk,
           const float* __restrict__ bv,
           float* __restrict__ Cq, float* __restrict__ Ck, float* __restrict__ Cv) {
    int sel = blockIdx.x / 12;
    int colblk = blockIdx.x % 12;
    const __nv_bfloat16* Bm = (sel == 0) ? Bq : (sel == 1) ? Bk : Bv;
    const float* bias       = (sel == 0) ? bq : (sel == 1) ? bk : bv;
    float*       Cm         = (sel == 0) ? Cq : (sel == 1) ? Ck : Cv;
    gemm_body<0, 0>(A, Bm, bias, nullptr, Cm, BT, CC, CC,
                    blockIdx.y * 128, colblk * 64);
}

// ---------------- banded rel-pos attention (tf32 tensor-core, bf16 out) ----------------
#define TQ 16
#define SRR 120

#define OF_KV 0
#define KVST  72
#define KST   68
#define OF_QU 8640
#define QST   68
#define OF_QV 9728
#define OF_PS 10816
#define PST   68
#define OF_S1 17888
#define S1ST  132
#define OF_SC 20000
#define SCST  104
#define ATTN_SMEM_BYTES (21664 * 4)

__global__ void __launch_bounds__(256)
attn_kernel(const float* __restrict__ q, const float* __restrict__ k,
            const float* __restrict__ v, const float* __restrict__ pc,
            const float* __restrict__ pu, const float* __restrict__ pv,
            __nv_bfloat16* __restrict__ o) {
    extern __shared__ float sm[];
    float* KV = sm + OF_KV;
    float* QU = sm + OF_QU;
    float* QV = sm + OF_QV;
    float* PS = sm + OF_PS;
    float* S1 = sm + OF_S1;
    float* SC = sm + OF_SC;

    const int b  = blockIdx.z;
    const int h  = blockIdx.y;
    const int t0 = blockIdx.x * TQ;
    const int sbase = t0 - WHALF;
    const int tid = threadIdx.x;
    const int warp = tid >> 5, lane = tid & 31;
    const int g = lane >> 2, t4 = lane & 3;

    for (int e = tid; e < TQ * 16; e += 256) {
        int qi = e >> 4, d4 = (e & 15) * 4;
        int tt = t0 + qi;
        float4 qq = make_float4(0.f, 0.f, 0.f, 0.f);
        if (tt < TT) qq = *(const float4*)(q + ((size_t)(b*TT+tt))*CC + h*DKK + d4);
        float4 u4 = *(const float4*)(pu + h*DKK + d4);
        float4 v4 = *(const float4*)(pv + h*DKK + d4);
        *(float4*)(QU + qi*QST + d4) = make_float4(qq.x+u4.x, qq.y+u4.y, qq.z+u4.z, qq.w+u4.w);
        *(float4*)(QV + qi*QST + d4) = make_float4(qq.x+v4.x, qq.y+v4.y, qq.z+v4.z, qq.w+v4.w);
    }
    for (int e = tid; e < SRR * 16; e += 256) {
        int si = e >> 4, d4 = (e & 15) * 4;
        int s = sbase + si;
        float4 kk = make_float4(0.f, 0.f, 0.f, 0.f);
        if (s >= 0 && s < TT) kk = *(const float4*)(k + ((size_t)(b*TT+s))*CC + h*DKK + d4);
        *(float4*)(KV + si*KST + d4) = kk;
    }
    for (int e = tid; e < 104 * 16; e += 256) {
        int r = e >> 4, d4 = (e & 15) * 4;
        float4 pp = make_float4(0.f, 0.f, 0.f, 0.f);
        if (r < NR) pp = *(const float4*)(pc + (size_t)r*CC + h*DKK + d4);
        *(float4*)(PS + r*PST + d4) = pp;
    }
    __syncthreads();

    for (int nt = warp; nt < 15; nt += 8) {
        float c[4] = {0.f, 0.f, 0.f, 0.f};
        #pragma unroll
        for (int ch = 0; ch < 8; ch++) {
            uint4 a;
            a.x = __float_as_uint(QU[g*QST + ch*8 + t4]);
            a.y = __float_as_uint(QU[(g+8)*QST + ch*8 + t4]);
            a.z = __float_as_uint(QU[g*QST + ch*8 + t4 + 4]);
            a.w = __float_as_uint(QU[(g+8)*QST + ch*8 + t4 + 4]);
            uint2 bq;
            bq.x = __float_as_uint(KV[(nt*8+g)*KST + ch*8 + t4]);
            bq.y = __float_as_uint(KV[(nt*8+g)*KST + ch*8 + t4 + 4]);
            mma_tf32(c, a, bq);
        }
        *(float2*)(S1 + g*S1ST + nt*8 + 2*t4)     = make_float2(c[0], c[1]);
        *(float2*)(S1 + (g+8)*S1ST + nt*8 + 2*t4) = make_float2(c[2], c[3]);
    }
    for (int nt = warp; nt < 13; nt += 8) {
        float c[4] = {0.f, 0.f, 0.f, 0.f};
        #pragma unroll
        for (int ch = 0; ch < 8; ch++) {
            uint4 a;
            a.x = __float_as_uint(QV[g*QST + ch*8 + t4]);
            a.y = __float_as_uint(QV[(g+8)*QST + ch*8 + t4]);
            a.z = __float_as_uint(QV[g*QST + ch*8 + t4 + 4]);
            a.w = __float_as_uint(QV[(g+8)*QST + ch*8 + t4 + 4]);
            uint2 bq;
            bq.x = __float_as_uint(PS[(nt*8+g)*PST + ch*8 + t4]);
            bq.y = __float_as_uint(PS[(nt*8+g)*PST + ch*8 + t4 + 4]);
            mma_tf32(c, a, bq);
        }
        *(float2*)(SC + g*SCST + nt*8 + 2*t4)     = make_float2(c[0], c[1]);
        *(float2*)(SC + (g+8)*SCST + nt*8 + 2*t4) = make_float2(c[2], c[3]);
    }
    __syncthreads();

    for (int e = tid; e < TQ * NR; e += 256) {
        int qi = e & 15, r = e >> 4;
        int tt = t0 + qi, s = tt + r - WHALF;
        float val = -1e30f;
        if (tt < TT && s >= 0 && s < TT)
            val = (S1[qi*S1ST + qi + r] + SC[qi*SCST + r]) * 0.125f;
        SC[qi*SCST + r] = val;
    }
    for (int e = tid; e < SRR * 16; e += 256) {
        int si = e >> 4, d4 = (e & 15) * 4;
        int s = sbase + si;
        float4 vv = make_float4(0.f, 0.f, 0.f, 0.f);
        if (s >= 0 && s < TT) vv = *(const float4*)(v + ((size_t)(b*TT+s))*CC + h*DKK + d4);
        *(float4*)(KV + si*KVST + d4) = vv;
    }
    __syncthreads();

    for (int e = tid; e < TQ * S1ST; e += 256) S1[e] = 0.f;
    if (tid < TQ) {
        float* srow = SC + tid * SCST;
        float m = -1e30f;
        for (int r = 0; r < NR; r++) m = fmaxf(m, srow[r]);
        float sum = 0.f;
        for (int r = 0; r < NR; r++) { float ev = __expf(srow[r] - m); srow[r] = ev; sum += ev; }
        float inv = 1.f / sum;
        for (int r = 0; r < NR; r++) srow[r] *= inv;
    }
    __syncthreads();

    for (int e = tid; e < TQ * NR; e += 256) {
        int qi = e & 15, r = e >> 4;
        S1[qi*S1ST + qi + r] = SC[qi*SCST + r];
    }
    __syncthreads();

    {
        int n0 = warp * 8;
        float c[4] = {0.f, 0.f, 0.f, 0.f};
        #pragma unroll
        for (int ch = 0; ch < 15; ch++) {
            uint4 a;
            a.x = __float_as_uint(S1[g*S1ST + ch*8 + t4]);
            a.y = __float_as_uint(S1[(g+8)*S1ST + ch*8 + t4]);
            a.z = __float_as_uint(S1[g*S1ST + ch*8 + t4 + 4]);
            a.w = __float_as_uint(S1[(g+8)*S1ST + ch*8 + t4 + 4]);
            uint2 bq;
            bq.x = __float_as_uint(KV[(ch*8+t4)*KVST + n0 + g]);
            bq.y = __float_as_uint(KV[(ch*8+t4+4)*KVST + n0 + g]);
            mma_tf32(c, a, bq);
        }
        int tg0 = t0 + g, tg1 = t0 + g + 8;
        if (tg0 < TT) {
            __nv_bfloat162 p; p.x = __float2bfloat16(c[0]); p.y = __float2bfloat16(c[1]);
            *(__nv_bfloat162*)(o + ((size_t)(b*TT+tg0))*CC + h*DKK + n0 + 2*t4) = p;
        }
        if (tg1 < TT) {
            __nv_bfloat162 p; p.x = __float2bfloat16(c[2]); p.y = __float2bfloat16(c[3]);
            *(__nv_bfloat162*)(o + ((size_t)(b*TT+tg1))*CC + h*DKK + n0 + 2*t4) = p;
        }
    }
}

// ---------------- driver ----------------
extern "C" void kernel_launch(void* const* d_in, const int* in_sizes, int n_in,
                              void* d_out, int out_size) {
    const float* x    = (const float*)d_in[0];
    const float* Wq   = (const float*)d_in[1];
    const float* bq   = (const float*)d_in[2];
    const float* Wk   = (const float*)d_in[3];
    const float* bk   = (const float*)d_in[4];
    const float* Wv   = (const float*)d_in[5];
    const float* bv   = (const float*)d_in[6];
    const float* Wo   = (const float*)d_in[7];
    const float* bo   = (const float*)d_in[8];
    const float* Wp   = (const float*)d_in[9];
    const float* pu   = (const float*)d_in[10];
    const float* pvv  = (const float*)d_in[11];
    const float* ln1g = (const float*)d_in[12];
    const float* ln1b = (const float*)d_in[13];
    const float* ln2g = (const float*)d_in[14];
    const float* ln2b = (const float*)d_in[15];
    const float* W1   = (const float*)d_in[16];
    const float* b1   = (const float*)d_in[17];
    const float* W2   = (const float*)d_in[18];
    const float* b2   = (const float*)d_in[19];
    // d_in[20] = att_mask: fixed band |i-j|>50, handled analytically.

    float *h, *q, *k, *v, *pc;
    __nv_bfloat16 *ybf, *obf, *pebf, *wbf;
    cudaGetSymbolAddress((void**)&h,    g_h);
    cudaGetSymbolAddress((void**)&q,    g_q);
    cudaGetSymbolAddress((void**)&k,    g_k);
    cudaGetSymbolAddress((void**)&v,    g_v);
    cudaGetSymbolAddress((void**)&pc,   g_pc);
    cudaGetSymbolAddress((void**)&ybf,  g_ybf);
    cudaGetSymbolAddress((void**)&obf,  g_obf);
    cudaGetSymbolAddress((void**)&pebf, g_pebf);
    cudaGetSymbolAddress((void**)&wbf,  g_wbf);

    cudaFuncSetAttribute(attn_kernel, cudaFuncAttributeMaxDynamicSharedMemorySize, ATTN_SMEM_BYTES);

    const int WSZ = LNUM * CC * CC;   // elements per weight tensor (all layers)
    const int cgrid = (WSZ + 255) / 256;
    f2b_kernel<<<cgrid, 256>>>(Wq, wbf + 0 * WSZ, WSZ);
    f2b_kernel<<<cgrid, 256>>>(Wk, wbf + 1 * WSZ, WSZ);
    f2b_kernel<<<cgrid, 256>>>(Wv, wbf + 2 * WSZ, WSZ);
    f2b_kernel<<<cgrid, 256>>>(Wo, wbf + 3 * WSZ, WSZ);
    f2b_kernel<<<cgrid, 256>>>(Wp, wbf + 4 * WSZ, WSZ);
    f2b_kernel<<<cgrid, 256>>>(W1, wbf + 5 * WSZ, WSZ);
    f2b_kernel<<<cgrid, 256>>>(W2, wbf + 6 * WSZ, WSZ);

    init_h_kernel<<<(BT*CC + 255) / 256, 256>>>(x);
    pe_kernel<<<(NR*(CC/2) + 255) / 256, 256>>>();

    dim3 gBig(CC / 64, (BT + 127) / 128);        // (12, 32)
    dim3 gQKV(3 * (CC / 64), (BT + 127) / 128);  // (36, 32)
    dim3 gP  (CC / 64, 1);                       // (12, 1), M=101
    dim3 gAtt((TT + TQ - 1) / TQ, HH, BB);       // (63, 12, 4)

    for (int l = 0; l < LNUM; l++) {
        size_t wOff = (size_t)l * CC * CC;
        size_t bOff = (size_t)l * CC;

        ln_kernel<<<BT, 256>>>(h, ybf, ln1g + bOff, ln1b + bOff);
        qkv_kernel<<<gQKV, 256, GEMM_SMEM>>>(ybf,
            wbf + 0*WSZ + wOff, wbf + 1*WSZ + wOff, wbf + 2*WSZ + wOff,
            bq + bOff, bk + bOff, bv + bOff, q, k, v);
        tgemm_kernel<0,0><<<gP, 256, GEMM_SMEM>>>(pebf, wbf + 4*WSZ + wOff,
            nullptr, nullptr, pc, NR, CC, CC);
        attn_kernel<<<gAtt, 256, ATTN_SMEM_BYTES>>>(q, k, v, pc, pu + bOff, pvv + bOff, obf);
        tgemm_kernel<2,0><<<gBig, 256, GEMM_SMEM>>>(obf, wbf + 3*WSZ + wOff,
            bo + bOff, h, h, BT, CC, CC);
        ln_kernel<<<BT, 256>>>(h, ybf, ln2g + bOff, ln2b + bOff);
        tgemm_kernel<1,1><<<gBig, 256, GEMM_SMEM>>>(ybf, wbf + 5*WSZ + wOff,
            b1 + bOff, nullptr, obf, BT, CC, CC);
        void* outp = (l == LNUM - 1) ? d_out : (void*)h;
        tgemm_kernel<2,0><<<gBig, 256, GEMM_SMEM>>>(obf, wbf + 6*WSZ + wOff,
            b2 + bOff, h, outp, BT, CC, CC);
    }
}

// round 10
// speedup vs baseline: 3.7161x; 1.2667x over previous
#include <cuda_runtime.h>
#include <cuda_bf16.h>
#include <math.h>
#include <stdint.h>

// ---------------- problem constants ----------------
#define LNUM 2
#define BB   4
#define TT   1000
#define CC   768
#define HH   12
#define DKK  64
#define WHALF 50         // band half-width (WIN//2)
#define NR   101         // relative positions actually reachable: -50..50
#define BT   (BB*TT)     // 4000 rows
#define WSZ  (LNUM*CC*CC)

// ---------------- device scratch (no allocs allowed) ----------------
__device__ float g_h[BT*CC];
__device__ __nv_bfloat16 g_ybf[BT*CC];        // LN output (GEMM A operand)
__device__ __nv_bfloat16 g_obf[BT*CC];        // attn out / gelu out (GEMM A operand)
__device__ __nv_bfloat16 g_qb[BT*CC];
__device__ __nv_bfloat16 g_kb[BT*CC];
__device__ __nv_bfloat16 g_vb[BT*CC];
__device__ __nv_bfloat16 g_pcb[NR*CC];        // pe @ Wp[l], bf16
__device__ __nv_bfloat16 g_pebf[NR*CC];       // positional table, bf16
__device__ __nv_bfloat16 g_wbf[7*WSZ];        // bf16 weights: Wq,Wk,Wv,Wo,Wp,W1,W2

// ---------------- small kernels ----------------
__global__ void init_h_kernel(const float* __restrict__ x) {
    int i = blockIdx.x * blockDim.x + threadIdx.x;
    if (i < BT*CC) g_h[i] = x[i] * 27.712812921102035f;  // sqrt(768)
}

// one kernel converts all 7 weight tensors fp32 -> bf16 (float4 vectorized)
__global__ void f2b_all_kernel(const float* __restrict__ s0, const float* __restrict__ s1,
                               const float* __restrict__ s2, const float* __restrict__ s3,
                               const float* __restrict__ s4, const float* __restrict__ s5,
                               const float* __restrict__ s6) {
    const int per = WSZ / 4;                       // float4 chunks per tensor
    int i4 = blockIdx.x * blockDim.x + threadIdx.x;
    int t = i4 / per;
    int off = i4 - t * per;
    const float* src = (t == 0) ? s0 : (t == 1) ? s1 : (t == 2) ? s2 :
                       (t == 3) ? s3 : (t == 4) ? s4 : (t == 5) ? s5 : s6;
    float4 vv = ((const float4*)src)[off];
    __nv_bfloat162 a, b;
    a.x = __float2bfloat16(vv.x); a.y = __float2bfloat16(vv.y);
    b.x = __float2bfloat16(vv.z); b.y = __float2bfloat16(vv.w);
    __nv_bfloat162* dst = (__nv_bfloat162*)(g_wbf + (size_t)t * WSZ);
    dst[off * 2]     = a;
    dst[off * 2 + 1] = b;
}

__global__ void pe_kernel() {
    int i = blockIdx.x * blockDim.x + threadIdx.x;
    if (i < NR*(CC/2)) {
        int r = i / (CC/2);
        int j = i % (CC/2);
        float div = expf(-(float)(2*j) * (9.210340371976184f / (float)CC)); // ln(10000)/C
        float ang = (float)(WHALF - r) * div;   // rel = -(r-50)
        g_pebf[r*CC + 2*j]     = __float2bfloat16(sinf(ang));
        g_pebf[r*CC + 2*j + 1] = __float2bfloat16(cosf(ang));
    }
}

// LayerNorm: fp32 in, bf16 out
__global__ void ln_kernel(const float* __restrict__ in, __nv_bfloat16* __restrict__ out,
                          const float* __restrict__ g, const float* __restrict__ b) {
    int row = blockIdx.x;
    const float* xr = in + (size_t)row * CC;
    float s = 0.f, s2 = 0.f;
    for (int i = threadIdx.x; i < CC; i += 256) {
        float v = xr[i];
        s += v; s2 += v * v;
    }
    __shared__ float sh[16];
    #pragma unroll
    for (int o = 16; o; o >>= 1) {
        s  += __shfl_xor_sync(0xffffffffu, s,  o);
        s2 += __shfl_xor_sync(0xffffffffu, s2, o);
    }
    int w = threadIdx.x >> 5;
    if ((threadIdx.x & 31) == 0) { sh[w] = s; sh[8 + w] = s2; }
    __syncthreads();
    s = 0.f; s2 = 0.f;
    #pragma unroll
    for (int i = 0; i < 8; i++) { s += sh[i]; s2 += sh[8 + i]; }
    float mean = s * (1.f / CC);
    float var  = s2 * (1.f / CC) - mean * mean;
    float rstd = rsqrtf(var + 1e-5f);
    __nv_bfloat16* orow = out + (size_t)row * CC;
    for (int i = threadIdx.x; i < CC; i += 256)
        orow[i] = __float2bfloat16((xr[i] - mean) * rstd * g[i] + b[i]);
}

// ---------------- mma / ldmatrix / cp.async helpers ----------------
__device__ __forceinline__ void mma_bf16(float c[4], const uint4& a, uint32_t b0, uint32_t b1) {
    asm volatile(
        "mma.sync.aligned.m16n8k16.row.col.f32.bf16.bf16.f32 "
        "{%0,%1,%2,%3}, {%4,%5,%6,%7}, {%8,%9}, {%0,%1,%2,%3};"
        : "+f"(c[0]), "+f"(c[1]), "+f"(c[2]), "+f"(c[3])
        : "r"(a.x), "r"(a.y), "r"(a.z), "r"(a.w), "r"(b0), "r"(b1));
}
__device__ __forceinline__ void ldsm_x4(uint4& d, uint32_t addr) {
    asm volatile("ldmatrix.sync.aligned.m8n8.x4.shared.b16 {%0,%1,%2,%3}, [%4];"
                 : "=r"(d.x), "=r"(d.y), "=r"(d.z), "=r"(d.w) : "r"(addr));
}
__device__ __forceinline__ void ldsm_x4_t(uint4& d, uint32_t addr) {
    asm volatile("ldmatrix.sync.aligned.m8n8.x4.trans.shared.b16 {%0,%1,%2,%3}, [%4];"
                 : "=r"(d.x), "=r"(d.y), "=r"(d.z), "=r"(d.w) : "r"(addr));
}
__device__ __forceinline__ void cp16(uint32_t dst, const void* src, int srcsize) {
    asm volatile("cp.async.cg.shared.global [%0], [%1], 16, %2;\n"
                 :: "r"(dst), "l"(src), "r"(srcsize));
}
__device__ __forceinline__ void cp_commit() {
    asm volatile("cp.async.commit_group;\n");
}
template<int N> __device__ __forceinline__ void cp_wait() {
    asm volatile("cp.async.wait_group %0;\n" :: "n"(N));
}

__device__ __forceinline__ float gelu_f(float x) {
    float x3 = x * x * x;
    return 0.5f * x * (1.f + tanhf(0.7978845608028654f * (x + 0.044715f * x3)));
}

// ---------------- bf16 tensor-core GEMM, 3-stage cp.async ----------------
#define AST2 20
#define BST2 36
#define STG_A (128*AST2)   // 2560 u32
#define STG_B (32*BST2)    // 1152 u32
#define GEMM_SMEM (3*(STG_A+STG_B)*4)   // 44544 bytes

template<int EPI, int OUTBF>
__device__ __forceinline__ void gemm_body(
        const __nv_bfloat16* __restrict__ A, const __nv_bfloat16* __restrict__ Bm,
        const float* __restrict__ bias, const float* __restrict__ resid,
        void* __restrict__ Cm, int M, int N, int K, int row0, int col0) {
    extern __shared__ uint32_t smu[];
    const uint32_t smem_base = (uint32_t)__cvta_generic_to_shared(smu);

    const int tid  = threadIdx.x;
    const int warp = tid >> 5;
    const int lane = tid & 31;
    const int g    = lane >> 2;
    const int t    = lane & 3;
    const int wr   = warp >> 1;
    const int wc   = warp & 1;

    float acc[2][4][4];
    #pragma unroll
    for (int i = 0; i < 2; i++)
        #pragma unroll
        for (int j = 0; j < 4; j++)
            #pragma unroll
            for (int r = 0; r < 4; r++) acc[i][j][r] = 0.f;

    const int a_r = tid >> 2, a_c = tid & 3;
    const int b_r = tid >> 3, b_c = tid & 7;

#define LOADS(s_) do {                                                              \
        const int k0_ = (s_) * 32;                                                  \
        uint32_t* Ab_ = smu + ((s_) % 3) * (STG_A + STG_B);                         \
        uint32_t* Bb_ = Ab_ + STG_A;                                                \
        _Pragma("unroll")                                                           \
        for (int i_ = 0; i_ < 2; i_++) {                                            \
            int r_ = a_r + i_ * 64;                                                 \
            int gr_ = row0 + r_;                                                    \
            int ok_ = (gr_ < M) ? 16 : 0;                                           \
            const __nv_bfloat16* src_ = A + (size_t)(ok_ ? gr_ : 0) * K + k0_ + a_c * 8; \
            cp16((uint32_t)__cvta_generic_to_shared(Ab_ + r_ * AST2 + a_c * 4), src_, ok_); \
        }                                                                           \
        {                                                                           \
            const __nv_bfloat16* src_ = Bm + (size_t)(k0_ + b_r) * N + col0 + b_c * 8;   \
            cp16((uint32_t)__cvta_generic_to_shared(Bb_ + b_r * BST2 + b_c * 4), src_, 16); \
        }                                                                           \
    } while (0)

    const int steps = K >> 5;
    LOADS(0); cp_commit();
    LOADS(1); cp_commit();

    const int a_lane_off = (lane & 15) * AST2 + (lane >> 4) * 4;
    const int b_lane_off = (lane & 15) * BST2 + wc * 16 + (lane >> 4) * 4;

    for (int s = 0; s < steps; s++) {
        cp_wait<1>();
        __syncthreads();
        if (s + 2 < steps) LOADS(s + 2);
        cp_commit();

        const uint32_t bufo = (uint32_t)((s % 3) * (STG_A + STG_B));
        const uint32_t abase = smem_base + (bufo + wr * 32 * AST2 + a_lane_off) * 4;
        const uint32_t bbase = smem_base + (bufo + STG_A + b_lane_off) * 4;

        #pragma unroll
        for (int ch = 0; ch < 2; ch++) {
            uint4 af[2];
            #pragma unroll
            for (int i = 0; i < 2; i++)
                ldsm_x4(af[i], abase + (i * 16 * AST2 + ch * 8) * 4);
            uint4 bq[2];
            #pragma unroll
            for (int jj = 0; jj < 2; jj++)
                ldsm_x4_t(bq[jj], bbase + (ch * 16 * BST2 + jj * 8) * 4);
            #pragma unroll
            for (int i = 0; i < 2; i++) {
                mma_bf16(acc[i][0], af[i], bq[0].x, bq[0].y);
                mma_bf16(acc[i][1], af[i], bq[0].z, bq[0].w);
                mma_bf16(acc[i][2], af[i], bq[1].x, bq[1].y);
                mma_bf16(acc[i][3], af[i], bq[1].z, bq[1].w);
            }
        }
    }
#undef LOADS

    __syncthreads();

    #pragma unroll
    for (int i = 0; i < 2; i++) {
        int rbase = row0 + wr * 32 + i * 16 + g;
        #pragma unroll
        for (int j = 0; j < 4; j++) {
            int col = col0 + wc * 32 + j * 8 + t * 2;
            float bx = 0.f, by = 0.f;
            if (bias) { bx = bias[col]; by = bias[col + 1]; }
            #pragma unroll
            for (int hh = 0; hh < 2; hh++) {
                int row = rbase + hh * 8;
                if (row < M) {
                    float c0 = acc[i][j][hh * 2 + 0] + bx;
                    float c1 = acc[i][j][hh * 2 + 1] + by;
                    if (EPI == 1) { c0 = gelu_f(c0); c1 = gelu_f(c1); }
                    if (EPI == 2) {
                        float2 rv = *(const float2*)(resid + (size_t)row * N + col);
                        c0 += rv.x; c1 += rv.y;
                    }
                    if (OUTBF) {
                        __nv_bfloat162 p;
                        p.x = __float2bfloat16(c0);
                        p.y = __float2bfloat16(c1);
                        *(__nv_bfloat162*)((__nv_bfloat16*)Cm + (size_t)row * N + col) = p;
                    } else {
                        *(float2*)((float*)Cm + (size_t)row * N + col) = make_float2(c0, c1);
                    }
                }
            }
        }
    }
}

template<int EPI, int OUTBF>
__global__ void __launch_bounds__(256)
tgemm_kernel(const __nv_bfloat16* __restrict__ A, const __nv_bfloat16* __restrict__ Bm,
             const float* __restrict__ bias, const float* __restrict__ resid,
             void* __restrict__ Cm, int M, int N, int K) {
    gemm_body<EPI, OUTBF>(A, Bm, bias, resid, Cm, M, N, K,
                          blockIdx.y * 128, blockIdx.x * 64);
}

__global__ void __launch_bounds__(256)
qkv_kernel(const __nv_bfloat16* __restrict__ A,
           const __nv_bfloat16* __restrict__ Bq, const __nv_bfloat16* __restrict__ Bk,
           const __nv_bfloat16* __restrict__ Bv,
           const float* __restrict__ bq, const float* __restrict__ bk,
           const float* __restrict__ bv,
           __nv_bfloat16* __restrict__ Cq, __nv_bfloat16* __restrict__ Ck,
           __nv_bfloat16* __restrict__ Cv) {
    int sel = blockIdx.x / 12;
    int colblk = blockIdx.x % 12;
    const __nv_bfloat16* Bm = (sel == 0) ? Bq : (sel == 1) ? Bk : Bv;
    const float* bias       = (sel == 0) ? bq : (sel == 1) ? bk : bv;
    __nv_bfloat16* Cm       = (sel == 0) ? Cq : (sel == 1) ? Ck : Cv;
    gemm_body<0, 1>(A, Bm, bias, nullptr, Cm, BT, CC, CC,
                    blockIdx.y * 128, colblk * 64);
}

// ---------------- banded rel-pos attention (bf16 tensor-core) ----------------
// Per block: (b, h, 16 queries).
//  GEMM1: S1'[16][120] = QU(16x64) @ K^T    (bf16 mma, scalar CF fragment LDS)
//  GEMM2: SC'[16][104] = QV(16x64) @ P^T
//  combine+mask -> softmax -> scatter bf16 into shifted AT[16][128]
//  GEMM3: O[16][64] = AT @ V(128x64)        (B via ldmatrix.trans, warps 0-3)
// u32 strides: QU/QV/K/P/V = 36 (mod 32 = 4), AT = 68 (mod 32 = 4) -> CF.
#define TQ 16

#define U_KV 0            // 128 rows x 36 u32 (K, then V)
#define U_QU 4608         // 16 x 36
#define U_QV 5184         // 16 x 36
#define U_PS 5760         // 104 x 36
#define U_S1 9504         // fp32 16 x 132
#define U_SC 11616        // fp32 16 x 104
#define U_AT 13280        // bf16 16 x 68 u32 (= 136 bf16 cols)
#define ATTN_U32 14368
#define ATTN_SMEM_BYTES (ATTN_U32*4)

__global__ void __launch_bounds__(256)
attn_kernel(const __nv_bfloat16* __restrict__ q, const __nv_bfloat16* __restrict__ k,
            const __nv_bfloat16* __restrict__ v, const __nv_bfloat16* __restrict__ pc,
            const float* __restrict__ pu, const float* __restrict__ pv,
            __nv_bfloat16* __restrict__ o) {
    extern __shared__ uint32_t su[];
    uint32_t* KV  = su + U_KV;
    uint32_t* QUb = su + U_QU;
    uint32_t* QVb = su + U_QV;
    uint32_t* PSb = su + U_PS;
    float*    S1  = (float*)(su + U_S1);
    float*    SC  = (float*)(su + U_SC);
    uint32_t* AT  = su + U_AT;
    const uint32_t smem_base = (uint32_t)__cvta_generic_to_shared(su);

    const int b  = blockIdx.z;
    const int h  = blockIdx.y;
    const int t0 = blockIdx.x * TQ;
    const int sb = t0 - WHALF;
    const int tid = threadIdx.x;
    const int warp = tid >> 5, lane = tid & 31;
    const int g = lane >> 2, t4 = lane & 3;

    // ---- phase 1: stage QU/QV, K, P
    for (int e = tid; e < TQ * 32; e += 256) {
        int qi = e >> 5, cu = e & 31;
        int tt = t0 + qi;
        float f0 = 0.f, f1 = 0.f;
        if (tt < TT) {
            uint32_t raw = *(const uint32_t*)(q + ((size_t)(b*TT+tt))*CC + h*DKK + cu*2);
            __nv_bfloat162 p = *(__nv_bfloat162*)&raw;
            f0 = __bfloat162float(p.x); f1 = __bfloat162float(p.y);
        }
        float u0 = pu[h*DKK + cu*2], u1 = pu[h*DKK + cu*2 + 1];
        float w0 = pv[h*DKK + cu*2], w1 = pv[h*DKK + cu*2 + 1];
        __nv_bfloat162 a, c;
        a.x = __float2bfloat16(f0 + u0); a.y = __float2bfloat16(f1 + u1);
        c.x = __float2bfloat16(f0 + w0); c.y = __float2bfloat16(f1 + w1);
        QUb[qi*36 + cu] = *(uint32_t*)&a;
        QVb[qi*36 + cu] = *(uint32_t*)&c;
    }
    for (int e = tid; e < 120 * 8; e += 256) {
        int si = e >> 3, c = e & 7;
        int s = sb + si;
        uint4 kk = make_uint4(0,0,0,0);
        if (s >= 0 && s < TT) kk = *(const uint4*)(k + ((size_t)(b*TT+s))*CC + h*DKK + c*8);
        *(uint4*)(KV + si*36 + c*4) = kk;
    }
    for (int e = tid; e < 104 * 8; e += 256) {
        int r = e >> 3, c = e & 7;
        uint4 pp = make_uint4(0,0,0,0);
        if (r < NR) pp = *(const uint4*)(pc + (size_t)r*CC + h*DKK + c*8);
        *(uint4*)(PSb + r*36 + c*4) = pp;
    }
    __syncthreads();

    // ---- phase 2: score GEMMs (A fragments hoisted)
    {
        uint4 af[4];
        #pragma unroll
        for (int ch = 0; ch < 4; ch++) {
            af[ch].x = QUb[g*36 + ch*8 + t4];
            af[ch].y = QUb[(g+8)*36 + ch*8 + t4];
            af[ch].z = QUb[g*36 + ch*8 + t4 + 4];
            af[ch].w = QUb[(g+8)*36 + ch*8 + t4 + 4];
        }
        for (int nt = warp; nt < 15; nt += 8) {
            float c[4] = {0.f, 0.f, 0.f, 0.f};
            #pragma unroll
            for (int ch = 0; ch < 4; ch++) {
                uint32_t b0 = KV[(nt*8+g)*36 + ch*8 + t4];
                uint32_t b1 = KV[(nt*8+g)*36 + ch*8 + t4 + 4];
                mma_bf16(c, af[ch], b0, b1);
            }
            *(float2*)(S1 + g*132 + nt*8 + 2*t4)     = make_float2(c[0], c[1]);
            *(float2*)(S1 + (g+8)*132 + nt*8 + 2*t4) = make_float2(c[2], c[3]);
        }
        #pragma unroll
        for (int ch = 0; ch < 4; ch++) {
            af[ch].x = QVb[g*36 + ch*8 + t4];
            af[ch].y = QVb[(g+8)*36 + ch*8 + t4];
            af[ch].z = QVb[g*36 + ch*8 + t4 + 4];
            af[ch].w = QVb[(g+8)*36 + ch*8 + t4 + 4];
        }
        for (int nt = warp; nt < 13; nt += 8) {
            float c[4] = {0.f, 0.f, 0.f, 0.f};
            #pragma unroll
            for (int ch = 0; ch < 4; ch++) {
                uint32_t b0 = PSb[(nt*8+g)*36 + ch*8 + t4];
                uint32_t b1 = PSb[(nt*8+g)*36 + ch*8 + t4 + 4];
                mma_bf16(c, af[ch], b0, b1);
            }
            *(float2*)(SC + g*104 + nt*8 + 2*t4)     = make_float2(c[0], c[1]);
            *(float2*)(SC + (g+8)*104 + nt*8 + 2*t4) = make_float2(c[2], c[3]);
        }
    }
    __syncthreads();

    // ---- phase 3a: combine+mask -> SC ; zero AT ; stage V (overwrites K)
    for (int e = tid; e < TQ * NR; e += 256) {
        int qi = e & 15, r = e >> 4;
        int tt = t0 + qi, s = tt + r - WHALF;
        float val = -1e30f;
        if (tt < TT && s >= 0 && s < TT)
            val = (S1[qi*132 + qi + r] + SC[qi*104 + r]) * 0.125f;
        SC[qi*104 + r] = val;
    }
    for (int e = tid; e < TQ * 68; e += 256) AT[e] = 0u;
    for (int e = tid; e < 128 * 8; e += 256) {
        int si = e >> 3, c = e & 7;
        int s = sb + si;
        uint4 vv = make_uint4(0,0,0,0);
        if (si < 120 && s >= 0 && s < TT)
            vv = *(const uint4*)(v + ((size_t)(b*TT+s))*CC + h*DKK + c*8);
        *(uint4*)(KV + si*36 + c*4) = vv;
    }
    __syncthreads();

    // ---- phase 3b: softmax (serial, 16 rows)
    if (tid < TQ) {
        float* srow = SC + tid * 104;
        float m = -1e30f;
        for (int r = 0; r < NR; r++) m = fmaxf(m, srow[r]);
        float sum = 0.f;
        for (int r = 0; r < NR; r++) { float ev = __expf(srow[r] - m); srow[r] = ev; sum += ev; }
        float inv = 1.f / sum;
        for (int r = 0; r < NR; r++) srow[r] *= inv;
    }
    __syncthreads();

    // ---- phase 3c: scatter bf16 weights into shifted AT
    for (int e = tid; e < TQ * NR; e += 256) {
        int qi = e & 15, r = e >> 4;
        ((__nv_bfloat16*)AT)[qi*136 + qi + r] = __float2bfloat16(SC[qi*104 + r]);
    }
    __syncthreads();

    // ---- phase 4: O = AT(16x128) @ V(128x64); warps 0-3, n16 each
    if (warp < 4) {
        int n0 = warp * 16;
        float c0[4] = {0.f,0.f,0.f,0.f};
        float c1[4] = {0.f,0.f,0.f,0.f};
        uint32_t vbase = smem_base + (U_KV + (lane & 15)*36 + (n0 >> 1) + (lane >> 4)*4) * 4;
        #pragma unroll
        for (int ch = 0; ch < 8; ch++) {
            uint4 a;
            a.x = AT[g*68 + ch*8 + t4];
            a.y = AT[(g+8)*68 + ch*8 + t4];
            a.z = AT[g*68 + ch*8 + t4 + 4];
            a.w = AT[(g+8)*68 + ch*8 + t4 + 4];
            uint4 bq;
            ldsm_x4_t(bq, vbase + (ch * 16 * 36) * 4);
            mma_bf16(c0, a, bq.x, bq.y);
            mma_bf16(c1, a, bq.z, bq.w);
        }
        int tg0 = t0 + g, tg1 = t0 + g + 8;
        if (tg0 < TT) {
            __nv_bfloat16* orow = o + ((size_t)(b*TT+tg0))*CC + h*DKK;
            __nv_bfloat162 p;
            p.x = __float2bfloat16(c0[0]); p.y = __float2bfloat16(c0[1]);
            *(__nv_bfloat162*)(orow + n0 + 2*t4) = p;
            p.x = __float2bfloat16(c1[0]); p.y = __float2bfloat16(c1[1]);
            *(__nv_bfloat162*)(orow + n0 + 8 + 2*t4) = p;
        }
        if (tg1 < TT) {
            __nv_bfloat16* orow = o + ((size_t)(b*TT+tg1))*CC + h*DKK;
            __nv_bfloat162 p;
            p.x = __float2bfloat16(c0[2]); p.y = __float2bfloat16(c0[3]);
            *(__nv_bfloat162*)(orow + n0 + 2*t4) = p;
            p.x = __float2bfloat16(c1[2]); p.y = __float2bfloat16(c1[3]);
            *(__nv_bfloat162*)(orow + n0 + 8 + 2*t4) = p;
        }
    }
}

// ---------------- driver ----------------
extern "C" void kernel_launch(void* const* d_in, const int* in_sizes, int n_in,
                              void* d_out, int out_size) {
    const float* x    = (const float*)d_in[0];
    const float* Wq   = (const float*)d_in[1];
    const float* bq   = (const float*)d_in[2];
    const float* Wk   = (const float*)d_in[3];
    const float* bk   = (const float*)d_in[4];
    const float* Wv   = (const float*)d_in[5];
    const float* bv   = (const float*)d_in[6];
    const float* Wo   = (const float*)d_in[7];
    const float* bo   = (const float*)d_in[8];
    const float* Wp   = (const float*)d_in[9];
    const float* pu   = (const float*)d_in[10];
    const float* pvv  = (const float*)d_in[11];
    const float* ln1g = (const float*)d_in[12];
    const float* ln1b = (const float*)d_in[13];
    const float* ln2g = (const float*)d_in[14];
    const float* ln2b = (const float*)d_in[15];
    const float* W1   = (const float*)d_in[16];
    const float* b1   = (const float*)d_in[17];
    const float* W2   = (const float*)d_in[18];
    const float* b2   = (const float*)d_in[19];
    // d_in[20] = att_mask: fixed band |i-j|>50, handled analytically.

    float* h;
    __nv_bfloat16 *ybf, *obf, *qb, *kb, *vb, *pcb, *pebf, *wbf;
    cudaGetSymbolAddress((void**)&h,    g_h);
    cudaGetSymbolAddress((void**)&ybf,  g_ybf);
    cudaGetSymbolAddress((void**)&obf,  g_obf);
    cudaGetSymbolAddress((void**)&qb,   g_qb);
    cudaGetSymbolAddress((void**)&kb,   g_kb);
    cudaGetSymbolAddress((void**)&vb,   g_vb);
    cudaGetSymbolAddress((void**)&pcb,  g_pcb);
    cudaGetSymbolAddress((void**)&pebf, g_pebf);
    cudaGetSymbolAddress((void**)&wbf,  g_wbf);

    cudaFuncSetAttribute(attn_kernel, cudaFuncAttributeMaxDynamicSharedMemorySize, ATTN_SMEM_BYTES);

    f2b_all_kernel<<<7 * (WSZ / 4) / 256, 256>>>(Wq, Wk, Wv, Wo, Wp, W1, W2);
    init_h_kernel<<<(BT*CC + 255) / 256, 256>>>(x);
    pe_kernel<<<(NR*(CC/2) + 255) / 256, 256>>>();

    dim3 gBig(CC / 64, (BT + 127) / 128);        // (12, 32)
    dim3 gQKV(3 * (CC / 64), (BT + 127) / 128);  // (36, 32)
    dim3 gP  (CC / 64, 1);                       // (12, 1), M=101
    dim3 gAtt((TT + TQ - 1) / TQ, HH, BB);       // (63, 12, 4)

    for (int l = 0; l < LNUM; l++) {
        size_t wOff = (size_t)l * CC * CC;
        size_t bOff = (size_t)l * CC;

        ln_kernel<<<BT, 256>>>(h, ybf, ln1g + bOff, ln1b + bOff);
        qkv_kernel<<<gQKV, 256, GEMM_SMEM>>>(ybf,
            wbf + 0*WSZ + wOff, wbf + 1*WSZ + wOff, wbf + 2*WSZ + wOff,
            bq + bOff, bk + bOff, bv + bOff, qb, kb, vb);
        tgemm_kernel<0,1><<<gP, 256, GEMM_SMEM>>>(pebf, wbf + 4*WSZ + wOff,
            nullptr, nullptr, pcb, NR, CC, CC);
        attn_kernel<<<gAtt, 256, ATTN_SMEM_BYTES>>>(qb, kb, vb, pcb, pu + bOff, pvv + bOff, obf);
        tgemm_kernel<2,0><<<gBig, 256, GEMM_SMEM>>>(obf, wbf + 3*WSZ + wOff,
            bo + bOff, h, h, BT, CC, CC);
        ln_kernel<<<BT, 256>>>(h, ybf, ln2g + bOff, ln2b + bOff);
        tgemm_kernel<1,1><<<gBig, 256, GEMM_SMEM>>>(ybf, wbf + 5*WSZ + wOff,
            b1 + bOff, nullptr, obf, BT, CC, CC);
        void* outp = (l == LNUM - 1) ? d_out : (void*)h;
        tgemm_kernel<2,0><<<gBig, 256, GEMM_SMEM>>>(obf, wbf + 6*WSZ + wOff,
            b2 + bOff, h, outp, BT, CC, CC);
    }
}

// round 11
// speedup vs baseline: 3.7187x; 1.0007x over previous
#include <cuda_runtime.h>
#include <cuda_bf16.h>
#include <math.h>
#include <stdint.h>

// ---------------- problem constants ----------------
#define LNUM 2
#define BB   4
#define TT   1000
#define CC   768
#define HH   12
#define DKK  64
#define WHALF 50         // band half-width (WIN//2)
#define NR   101         // relative positions actually reachable: -50..50
#define BT   (BB*TT)     // 4000 rows
#define WSZ  (LNUM*CC*CC)

// ---------------- device scratch (no allocs allowed) ----------------
__device__ float g_h[BT*CC];
__device__ __nv_bfloat16 g_ybf[BT*CC];        // LN output (GEMM A operand)
__device__ __nv_bfloat16 g_obf[BT*CC];        // attn out / gelu out (GEMM A operand)
__device__ __nv_bfloat16 g_qb[BT*CC];
__device__ __nv_bfloat16 g_kb[BT*CC];
__device__ __nv_bfloat16 g_vb[BT*CC];
__device__ __nv_bfloat16 g_pcb[NR*CC];        // pe @ Wp[l], bf16
__device__ __nv_bfloat16 g_pebf[NR*CC];       // positional table, bf16
__device__ __nv_bfloat16 g_wbf[7*WSZ];        // bf16 weights: Wq,Wk,Wv,Wo,Wp,W1,W2

// ---------------- small kernels ----------------
__global__ void init_h_kernel(const float* __restrict__ x) {
    int i = blockIdx.x * blockDim.x + threadIdx.x;
    if (i < BT*CC) g_h[i] = x[i] * 27.712812921102035f;  // sqrt(768)
}

// one kernel converts all 7 weight tensors fp32 -> bf16 (float4 vectorized)
__global__ void f2b_all_kernel(const float* __restrict__ s0, const float* __restrict__ s1,
                               const float* __restrict__ s2, const float* __restrict__ s3,
                               const float* __restrict__ s4, const float* __restrict__ s5,
                               const float* __restrict__ s6) {
    const int per = WSZ / 4;                       // float4 chunks per tensor
    int i4 = blockIdx.x * blockDim.x + threadIdx.x;
    int t = i4 / per;
    int off = i4 - t * per;
    const float* src = (t == 0) ? s0 : (t == 1) ? s1 : (t == 2) ? s2 :
                       (t == 3) ? s3 : (t == 4) ? s4 : (t == 5) ? s5 : s6;
    float4 vv = ((const float4*)src)[off];
    __nv_bfloat162 a, b;
    a.x = __float2bfloat16(vv.x); a.y = __float2bfloat16(vv.y);
    b.x = __float2bfloat16(vv.z); b.y = __float2bfloat16(vv.w);
    __nv_bfloat162* dst = (__nv_bfloat162*)(g_wbf + (size_t)t * WSZ);
    dst[off * 2]     = a;
    dst[off * 2 + 1] = b;
}

__global__ void pe_kernel() {
    int i = blockIdx.x * blockDim.x + threadIdx.x;
    if (i < NR*(CC/2)) {
        int r = i / (CC/2);
        int j = i % (CC/2);
        float div = expf(-(float)(2*j) * (9.210340371976184f / (float)CC)); // ln(10000)/C
        float ang = (float)(WHALF - r) * div;   // rel = -(r-50)
        g_pebf[r*CC + 2*j]     = __float2bfloat16(sinf(ang));
        g_pebf[r*CC + 2*j + 1] = __float2bfloat16(cosf(ang));
    }
}

// LayerNorm: fp32 in, bf16 out. float4 loads, bf16x4 stores. 1 row / block.
__global__ void ln_kernel(const float* __restrict__ in, __nv_bfloat16* __restrict__ out,
                          const float* __restrict__ g, const float* __restrict__ b) {
    const int row = blockIdx.x;
    const int tid = threadIdx.x;
    const float4* xr = (const float4*)(in + (size_t)row * CC);
    float4 vv = make_float4(0.f, 0.f, 0.f, 0.f);
    float s = 0.f, s2 = 0.f;
    if (tid < 192) {
        vv = xr[tid];
        s  = vv.x + vv.y + vv.z + vv.w;
        s2 = vv.x*vv.x + vv.y*vv.y + vv.z*vv.z + vv.w*vv.w;
    }
    __shared__ float sh[16];
    #pragma unroll
    for (int o = 16; o; o >>= 1) {
        s  += __shfl_xor_sync(0xffffffffu, s,  o);
        s2 += __shfl_xor_sync(0xffffffffu, s2, o);
    }
    int w = tid >> 5;
    if ((tid & 31) == 0) { sh[w] = s; sh[8 + w] = s2; }
    __syncthreads();
    s = 0.f; s2 = 0.f;
    #pragma unroll
    for (int i = 0; i < 8; i++) { s += sh[i]; s2 += sh[8 + i]; }
    float mean = s * (1.f / CC);
    float var  = s2 * (1.f / CC) - mean * mean;
    float rstd = rsqrtf(var + 1e-5f);
    if (tid < 192) {
        float4 g4 = ((const float4*)g)[tid];
        float4 b4 = ((const float4*)b)[tid];
        __nv_bfloat162 p0, p1;
        p0.x = __float2bfloat16((vv.x - mean) * rstd * g4.x + b4.x);
        p0.y = __float2bfloat16((vv.y - mean) * rstd * g4.y + b4.y);
        p1.x = __float2bfloat16((vv.z - mean) * rstd * g4.z + b4.z);
        p1.y = __float2bfloat16((vv.w - mean) * rstd * g4.w + b4.w);
        uint2 u;
        u.x = *(uint32_t*)&p0;
        u.y = *(uint32_t*)&p1;
        ((uint2*)(out + (size_t)row * CC))[tid] = u;
    }
}

// ---------------- mma / ldmatrix / cp.async helpers ----------------
__device__ __forceinline__ void mma_bf16(float c[4], const uint4& a, uint32_t b0, uint32_t b1) {
    asm volatile(
        "mma.sync.aligned.m16n8k16.row.col.f32.bf16.bf16.f32 "
        "{%0,%1,%2,%3}, {%4,%5,%6,%7}, {%8,%9}, {%0,%1,%2,%3};"
        : "+f"(c[0]), "+f"(c[1]), "+f"(c[2]), "+f"(c[3])
        : "r"(a.x), "r"(a.y), "r"(a.z), "r"(a.w), "r"(b0), "r"(b1));
}
__device__ __forceinline__ void ldsm_x4(uint4& d, uint32_t addr) {
    asm volatile("ldmatrix.sync.aligned.m8n8.x4.shared.b16 {%0,%1,%2,%3}, [%4];"
                 : "=r"(d.x), "=r"(d.y), "=r"(d.z), "=r"(d.w) : "r"(addr));
}
__device__ __forceinline__ void ldsm_x4_t(uint4& d, uint32_t addr) {
    asm volatile("ldmatrix.sync.aligned.m8n8.x4.trans.shared.b16 {%0,%1,%2,%3}, [%4];"
                 : "=r"(d.x), "=r"(d.y), "=r"(d.z), "=r"(d.w) : "r"(addr));
}
__device__ __forceinline__ void cp16(uint32_t dst, const void* src, int srcsize) {
    asm volatile("cp.async.cg.shared.global [%0], [%1], 16, %2;\n"
                 :: "r"(dst), "l"(src), "r"(srcsize));
}
__device__ __forceinline__ void cp_commit() {
    asm volatile("cp.async.commit_group;\n");
}
template<int N> __device__ __forceinline__ void cp_wait() {
    asm volatile("cp.async.wait_group %0;\n" :: "n"(N));
}

__device__ __forceinline__ float gelu_f(float x) {
    float x3 = x * x * x;
    return 0.5f * x * (1.f + tanhf(0.7978845608028654f * (x + 0.044715f * x3)));
}

// ---------------- bf16 tensor-core GEMM, 3-stage cp.async ----------------
// C(MxN) = A(MxK) @ B(KxN) [+bias] [epilogue]. BM=128, BN=128, BK=32 (bf16).
// 256 threads = 8 warps (2 row x 4 col), warp tile 64x32.
// A staged m-major, row stride 20 u32 -> CF ldmatrix.
// B staged k-major, row stride 68 u32 -> CF ldmatrix.trans.
#define AST2 20
#define BST2 68
#define STG_A (128*AST2)   // 2560 u32
#define STG_B (32*BST2)    // 2176 u32
#define GEMM_SMEM (3*(STG_A+STG_B)*4)   // 56832 bytes

template<int EPI, int OUTBF>
__device__ __forceinline__ void gemm_body(
        const __nv_bfloat16* __restrict__ A, const __nv_bfloat16* __restrict__ Bm,
        const float* __restrict__ bias, const float* __restrict__ resid,
        void* __restrict__ Cm, int M, int N, int K, int row0, int col0) {
    extern __shared__ uint32_t smu[];
    const uint32_t smem_base = (uint32_t)__cvta_generic_to_shared(smu);

    const int tid  = threadIdx.x;
    const int warp = tid >> 5;
    const int lane = tid & 31;
    const int g    = lane >> 2;
    const int t    = lane & 3;
    const int wr   = warp >> 2;    // 0..1 : 64 M-rows
    const int wc   = warp & 3;     // 0..3 : 32 N-cols

    float acc[4][4][4];
    #pragma unroll
    for (int i = 0; i < 4; i++)
        #pragma unroll
        for (int j = 0; j < 4; j++)
            #pragma unroll
            for (int r = 0; r < 4; r++) acc[i][j][r] = 0.f;

    const int a_r = tid >> 2, a_c = tid & 3;    // A: rows a_r, a_r+64; 4 chunks/row
    const int b_r = tid >> 4, b_c = tid & 15;   // B: rows b_r, b_r+16; 16 chunks/row

#define LOADS(s_) do {                                                              \
        const int k0_ = (s_) * 32;                                                  \
        uint32_t* Ab_ = smu + ((s_) % 3) * (STG_A + STG_B);                         \
        uint32_t* Bb_ = Ab_ + STG_A;                                                \
        _Pragma("unroll")                                                           \
        for (int i_ = 0; i_ < 2; i_++) {                                            \
            int r_ = a_r + i_ * 64;                                                 \
            int gr_ = row0 + r_;                                                    \
            int ok_ = (gr_ < M) ? 16 : 0;                                           \
            const __nv_bfloat16* src_ = A + (size_t)(ok_ ? gr_ : 0) * K + k0_ + a_c * 8; \
            cp16((uint32_t)__cvta_generic_to_shared(Ab_ + r_ * AST2 + a_c * 4), src_, ok_); \
        }                                                                           \
        _Pragma("unroll")                                                           \
        for (int i_ = 0; i_ < 2; i_++) {                                            \
            int r_ = b_r + i_ * 16;                                                 \
            const __nv_bfloat16* src_ = Bm + (size_t)(k0_ + r_) * N + col0 + b_c * 8;    \
            cp16((uint32_t)__cvta_generic_to_shared(Bb_ + r_ * BST2 + b_c * 4), src_, 16); \
        }                                                                           \
    } while (0)

    const int steps = K >> 5;
    LOADS(0); cp_commit();
    LOADS(1); cp_commit();

    const int a_lane_off = (lane & 15) * AST2 + (lane >> 4) * 4;
    const int b_lane_off = (lane & 15) * BST2 + wc * 16 + (lane >> 4) * 4;

    for (int s = 0; s < steps; s++) {
        cp_wait<1>();
        __syncthreads();
        if (s + 2 < steps) LOADS(s + 2);
        cp_commit();

        const uint32_t bufo = (uint32_t)((s % 3) * (STG_A + STG_B));
        const uint32_t abase = smem_base + (bufo + wr * 64 * AST2 + a_lane_off) * 4;
        const uint32_t bbase = smem_base + (bufo + STG_A + b_lane_off) * 4;

        #pragma unroll
        for (int ch = 0; ch < 2; ch++) {
            uint4 bq[2];
            #pragma unroll
            for (int jj = 0; jj < 2; jj++)
                ldsm_x4_t(bq[jj], bbase + (ch * 16 * BST2 + jj * 8) * 4);
            #pragma unroll
            for (int i = 0; i < 4; i++) {
                uint4 af;
                ldsm_x4(af, abase + (i * 16 * AST2 + ch * 8) * 4);
                mma_bf16(acc[i][0], af, bq[0].x, bq[0].y);
                mma_bf16(acc[i][1], af, bq[0].z, bq[0].w);
                mma_bf16(acc[i][2], af, bq[1].x, bq[1].y);
                mma_bf16(acc[i][3], af, bq[1].z, bq[1].w);
            }
        }
    }
#undef LOADS

    __syncthreads();

    #pragma unroll
    for (int i = 0; i < 4; i++) {
        int rbase = row0 + wr * 64 + i * 16 + g;
        #pragma unroll
        for (int j = 0; j < 4; j++) {
            int col = col0 + wc * 32 + j * 8 + t * 2;
            float bx = 0.f, by = 0.f;
            if (bias) { bx = bias[col]; by = bias[col + 1]; }
            #pragma unroll
            for (int hh = 0; hh < 2; hh++) {
                int row = rbase + hh * 8;
                if (row < M) {
                    float c0 = acc[i][j][hh * 2 + 0] + bx;
                    float c1 = acc[i][j][hh * 2 + 1] + by;
                    if (EPI == 1) { c0 = gelu_f(c0); c1 = gelu_f(c1); }
                    if (EPI == 2) {
                        float2 rv = *(const float2*)(resid + (size_t)row * N + col);
                        c0 += rv.x; c1 += rv.y;
                    }
                    if (OUTBF) {
                        __nv_bfloat162 p;
                        p.x = __float2bfloat16(c0);
                        p.y = __float2bfloat16(c1);
                        *(__nv_bfloat162*)((__nv_bfloat16*)Cm + (size_t)row * N + col) = p;
                    } else {
                        *(float2*)((float*)Cm + (size_t)row * N + col) = make_float2(c0, c1);
                    }
                }
            }
        }
    }
}

template<int EPI, int OUTBF>
__global__ void __launch_bounds__(256, 2)
tgemm_kernel(const __nv_bfloat16* __restrict__ A, const __nv_bfloat16* __restrict__ Bm,
             const float* __restrict__ bias, const float* __restrict__ resid,
             void* __restrict__ Cm, int M, int N, int K) {
    gemm_body<EPI, OUTBF>(A, Bm, bias, resid, Cm, M, N, K,
                          blockIdx.y * 128, blockIdx.x * 128);
}

__global__ void __launch_bounds__(256, 2)
qkv_kernel(const __nv_bfloat16* __restrict__ A,
           const __nv_bfloat16* __restrict__ Bq, const __nv_bfloat16* __restrict__ Bk,
           const __nv_bfloat16* __restrict__ Bv,
           const float* __restrict__ bq, const float* __restrict__ bk,
           const float* __restrict__ bv,
           __nv_bfloat16* __restrict__ Cq, __nv_bfloat16* __restrict__ Ck,
           __nv_bfloat16* __restrict__ Cv) {
    int sel = blockIdx.x / 6;
    int colblk = blockIdx.x % 6;
    const __nv_bfloat16* Bm = (sel == 0) ? Bq : (sel == 1) ? Bk : Bv;
    const float* bias       = (sel == 0) ? bq : (sel == 1) ? bk : bv;
    __nv_bfloat16* Cm       = (sel == 0) ? Cq : (sel == 1) ? Ck : Cv;
    gemm_body<0, 1>(A, Bm, bias, nullptr, Cm, BT, CC, CC,
                    blockIdx.y * 128, colblk * 128);
}

// ---------------- banded rel-pos attention (bf16 tensor-core) ----------------
#define TQ 16

#define U_KV 0            // 128 rows x 36 u32 (K, then V)
#define U_QU 4608         // 16 x 36
#define U_QV 5184         // 16 x 36
#define U_PS 5760         // 104 x 36
#define U_S1 9504         // fp32 16 x 132
#define U_SC 11616        // fp32 16 x 104
#define U_AT 13280        // bf16 16 x 68 u32 (= 136 bf16 cols)
#define ATTN_U32 14368
#define ATTN_SMEM_BYTES (ATTN_U32*4)

__global__ void __launch_bounds__(256)
attn_kernel(const __nv_bfloat16* __restrict__ q, const __nv_bfloat16* __restrict__ k,
            const __nv_bfloat16* __restrict__ v, const __nv_bfloat16* __restrict__ pc,
            const float* __restrict__ pu, const float* __restrict__ pv,
            __nv_bfloat16* __restrict__ o) {
    extern __shared__ uint32_t su[];
    uint32_t* KV  = su + U_KV;
    uint32_t* QUb = su + U_QU;
    uint32_t* QVb = su + U_QV;
    uint32_t* PSb = su + U_PS;
    float*    S1  = (float*)(su + U_S1);
    float*    SC  = (float*)(su + U_SC);
    uint32_t* AT  = su + U_AT;
    const uint32_t smem_base = (uint32_t)__cvta_generic_to_shared(su);

    const int b  = blockIdx.z;
    const int h  = blockIdx.y;
    const int t0 = blockIdx.x * TQ;
    const int sb = t0 - WHALF;
    const int tid = threadIdx.x;
    const int warp = tid >> 5, lane = tid & 31;
    const int g = lane >> 2, t4 = lane & 3;

    // ---- phase 1: stage QU/QV, K, P
    for (int e = tid; e < TQ * 32; e += 256) {
        int qi = e >> 5, cu = e & 31;
        int tt = t0 + qi;
        float f0 = 0.f, f1 = 0.f;
        if (tt < TT) {
            uint32_t raw = *(const uint32_t*)(q + ((size_t)(b*TT+tt))*CC + h*DKK + cu*2);
            __nv_bfloat162 p = *(__nv_bfloat162*)&raw;
            f0 = __bfloat162float(p.x); f1 = __bfloat162float(p.y);
        }
        float u0 = pu[h*DKK + cu*2], u1 = pu[h*DKK + cu*2 + 1];
        float w0 = pv[h*DKK + cu*2], w1 = pv[h*DKK + cu*2 + 1];
        __nv_bfloat162 a, c;
        a.x = __float2bfloat16(f0 + u0); a.y = __float2bfloat16(f1 + u1);
        c.x = __float2bfloat16(f0 + w0); c.y = __float2bfloat16(f1 + w1);
        QUb[qi*36 + cu] = *(uint32_t*)&a;
        QVb[qi*36 + cu] = *(uint32_t*)&c;
    }
    for (int e = tid; e < 120 * 8; e += 256) {
        int si = e >> 3, c = e & 7;
        int s = sb + si;
        uint4 kk = make_uint4(0,0,0,0);
        if (s >= 0 && s < TT) kk = *(const uint4*)(k + ((size_t)(b*TT+s))*CC + h*DKK + c*8);
        *(uint4*)(KV + si*36 + c*4) = kk;
    }
    for (int e = tid; e < 104 * 8; e += 256) {
        int r = e >> 3, c = e & 7;
        uint4 pp = make_uint4(0,0,0,0);
        if (r < NR) pp = *(const uint4*)(pc + (size_t)r*CC + h*DKK + c*8);
        *(uint4*)(PSb + r*36 + c*4) = pp;
    }
    __syncthreads();

    // ---- phase 2: score GEMMs (A fragments hoisted)
    {
        uint4 af[4];
        #pragma unroll
        for (int ch = 0; ch < 4; ch++) {
            af[ch].x = QUb[g*36 + ch*8 + t4];
            af[ch].y = QUb[(g+8)*36 + ch*8 + t4];
            af[ch].z = QUb[g*36 + ch*8 + t4 + 4];
            af[ch].w = QUb[(g+8)*36 + ch*8 + t4 + 4];
        }
        for (int nt = warp; nt < 15; nt += 8) {
            float c[4] = {0.f, 0.f, 0.f, 0.f};
            #pragma unroll
            for (int ch = 0; ch < 4; ch++) {
                uint32_t b0 = KV[(nt*8+g)*36 + ch*8 + t4];
                uint32_t b1 = KV[(nt*8+g)*36 + ch*8 + t4 + 4];
                mma_bf16(c, af[ch], b0, b1);
            }
            *(float2*)(S1 + g*132 + nt*8 + 2*t4)     = make_float2(c[0], c[1]);
            *(float2*)(S1 + (g+8)*132 + nt*8 + 2*t4) = make_float2(c[2], c[3]);
        }
        #pragma unroll
        for (int ch = 0; ch < 4; ch++) {
            af[ch].x = QVb[g*36 + ch*8 + t4];
            af[ch].y = QVb[(g+8)*36 + ch*8 + t4];
            af[ch].z = QVb[g*36 + ch*8 + t4 + 4];
            af[ch].w = QVb[(g+8)*36 + ch*8 + t4 + 4];
        }
        for (int nt = warp; nt < 13; nt += 8) {
            float c[4] = {0.f, 0.f, 0.f, 0.f};
            #pragma unroll
            for (int ch = 0; ch < 4; ch++) {
                uint32_t b0 = PSb[(nt*8+g)*36 + ch*8 + t4];
                uint32_t b1 = PSb[(nt*8+g)*36 + ch*8 + t4 + 4];
                mma_bf16(c, af[ch], b0, b1);
            }
            *(float2*)(SC + g*104 + nt*8 + 2*t4)     = make_float2(c[0], c[1]);
            *(float2*)(SC + (g+8)*104 + nt*8 + 2*t4) = make_float2(c[2], c[3]);
        }
    }
    __syncthreads();

    // ---- phase 3a: combine+mask -> SC ; zero AT ; stage V (overwrites K)
    for (int e = tid; e < TQ * NR; e += 256) {
        int qi = e & 15, r = e >> 4;
        int tt = t0 + qi, s = tt + r - WHALF;
        float val = -1e30f;
        if (tt < TT && s >= 0 && s < TT)
            val = (S1[qi*132 + qi + r] + SC[qi*104 + r]) * 0.125f;
        SC[qi*104 + r] = val;
    }
    for (int e = tid; e < TQ * 68; e += 256) AT[e] = 0u;
    for (int e = tid; e < 128 * 8; e += 256) {
        int si = e >> 3, c = e & 7;
        int s = sb + si;
        uint4 vv = make_uint4(0,0,0,0);
        if (si < 120 && s >= 0 && s < TT)
            vv = *(const uint4*)(v + ((size_t)(b*TT+s))*CC + h*DKK + c*8);
        *(uint4*)(KV + si*36 + c*4) = vv;
    }
    __syncthreads();

    // ---- phase 3b: softmax (serial, 16 rows)
    if (tid < TQ) {
        float* srow = SC + tid * 104;
        float m = -1e30f;
        for (int r = 0; r < NR; r++) m = fmaxf(m, srow[r]);
        float sum = 0.f;
        for (int r = 0; r < NR; r++) { float ev = __expf(srow[r] - m); srow[r] = ev; sum += ev; }
        float inv = 1.f / sum;
        for (int r = 0; r < NR; r++) srow[r] *= inv;
    }
    __syncthreads();

    // ---- phase 3c: scatter bf16 weights into shifted AT
    for (int e = tid; e < TQ * NR; e += 256) {
        int qi = e & 15, r = e >> 4;
        ((__nv_bfloat16*)AT)[qi*136 + qi + r] = __float2bfloat16(SC[qi*104 + r]);
    }
    __syncthreads();

    // ---- phase 4: O = AT(16x128) @ V(128x64); warps 0-3, n16 each
    if (warp < 4) {
        int n0 = warp * 16;
        float c0[4] = {0.f,0.f,0.f,0.f};
        float c1[4] = {0.f,0.f,0.f,0.f};
        uint32_t vbase = smem_base + (U_KV + (lane & 15)*36 + (n0 >> 1) + (lane >> 4)*4) * 4;
        #pragma unroll
        for (int ch = 0; ch < 8; ch++) {
            uint4 a;
            a.x = AT[g*68 + ch*8 + t4];
            a.y = AT[(g+8)*68 + ch*8 + t4];
            a.z = AT[g*68 + ch*8 + t4 + 4];
            a.w = AT[(g+8)*68 + ch*8 + t4 + 4];
            uint4 bq;
            ldsm_x4_t(bq, vbase + (ch * 16 * 36) * 4);
            mma_bf16(c0, a, bq.x, bq.y);
            mma_bf16(c1, a, bq.z, bq.w);
        }
        int tg0 = t0 + g, tg1 = t0 + g + 8;
        if (tg0 < TT) {
            __nv_bfloat16* orow = o + ((size_t)(b*TT+tg0))*CC + h*DKK;
            __nv_bfloat162 p;
            p.x = __float2bfloat16(c0[0]); p.y = __float2bfloat16(c0[1]);
            *(__nv_bfloat162*)(orow + n0 + 2*t4) = p;
            p.x = __float2bfloat16(c1[0]); p.y = __float2bfloat16(c1[1]);
            *(__nv_bfloat162*)(orow + n0 + 8 + 2*t4) = p;
        }
        if (tg1 < TT) {
            __nv_bfloat16* orow = o + ((size_t)(b*TT+tg1))*CC + h*DKK;
            __nv_bfloat162 p;
            p.x = __float2bfloat16(c0[2]); p.y = __float2bfloat16(c0[3]);
            *(__nv_bfloat162*)(orow + n0 + 2*t4) = p;
            p.x = __float2bfloat16(c1[2]); p.y = __float2bfloat16(c1[3]);
            *(__nv_bfloat162*)(orow + n0 + 8 + 2*t4) = p;
        }
    }
}

// ---------------- driver ----------------
extern "C" void kernel_launch(void* const* d_in, const int* in_sizes, int n_in,
                              void* d_out, int out_size) {
    const float* x    = (const float*)d_in[0];
    const float* Wq   = (const float*)d_in[1];
    const float* bq   = (const float*)d_in[2];
    const float* Wk   = (const float*)d_in[3];
    const float* bk   = (const float*)d_in[4];
    const float* Wv   = (const float*)d_in[5];
    const float* bv   = (const float*)d_in[6];
    const float* Wo   = (const float*)d_in[7];
    const float* bo   = (const float*)d_in[8];
    const float* Wp   = (const float*)d_in[9];
    const float* pu   = (const float*)d_in[10];
    const float* pvv  = (const float*)d_in[11];
    const float* ln1g = (const float*)d_in[12];
    const float* ln1b = (const float*)d_in[13];
    const float* ln2g = (const float*)d_in[14];
    const float* ln2b = (const float*)d_in[15];
    const float* W1   = (const float*)d_in[16];
    const float* b1   = (const float*)d_in[17];
    const float* W2   = (const float*)d_in[18];
    const float* b2   = (const float*)d_in[19];
    // d_in[20] = att_mask: fixed band |i-j|>50, handled analytically.

    float* h;
    __nv_bfloat16 *ybf, *obf, *qb, *kb, *vb, *pcb, *pebf, *wbf;
    cudaGetSymbolAddress((void**)&h,    g_h);
    cudaGetSymbolAddress((void**)&ybf,  g_ybf);
    cudaGetSymbolAddress((void**)&obf,  g_obf);
    cudaGetSymbolAddress((void**)&qb,   g_qb);
    cudaGetSymbolAddress((void**)&kb,   g_kb);
    cudaGetSymbolAddress((void**)&vb,   g_vb);
    cudaGetSymbolAddress((void**)&pcb,  g_pcb);
    cudaGetSymbolAddress((void**)&pebf, g_pebf);
    cudaGetSymbolAddress((void**)&wbf,  g_wbf);

    cudaFuncSetAttribute(tgemm_kernel<0,1>, cudaFuncAttributeMaxDynamicSharedMemorySize, GEMM_SMEM);
    cudaFuncSetAttribute(tgemm_kernel<1,1>, cudaFuncAttributeMaxDynamicSharedMemorySize, GEMM_SMEM);
    cudaFuncSetAttribute(tgemm_kernel<2,0>, cudaFuncAttributeMaxDynamicSharedMemorySize, GEMM_SMEM);
    cudaFuncSetAttribute(qkv_kernel,        cudaFuncAttributeMaxDynamicSharedMemorySize, GEMM_SMEM);
    cudaFuncSetAttribute(attn_kernel,       cudaFuncAttributeMaxDynamicSharedMemorySize, ATTN_SMEM_BYTES);

    f2b_all_kernel<<<7 * (WSZ / 4) / 256, 256>>>(Wq, Wk, Wv, Wo, Wp, W1, W2);
    init_h_kernel<<<(BT*CC + 255) / 256, 256>>>(x);
    pe_kernel<<<(NR*(CC/2) + 255) / 256, 256>>>();

    dim3 gBig(CC / 128, (BT + 127) / 128);       // (6, 32)
    dim3 gQKV(3 * (CC / 128), (BT + 127) / 128); // (18, 32)
    dim3 gP  (CC / 128, 1);                      // (6, 1), M=101
    dim3 gAtt((TT + TQ - 1) / TQ, HH, BB);       // (63, 12, 4)

    for (int l = 0; l < LNUM; l++) {
        size_t wOff = (size_t)l * CC * CC;
        size_t bOff = (size_t)l * CC;

        ln_kernel<<<BT, 256>>>(h, ybf, ln1g + bOff, ln1b + bOff);
        qkv_kernel<<<gQKV, 256, GEMM_SMEM>>>(ybf,
            wbf + 0*WSZ + wOff, wbf + 1*WSZ + wOff, wbf + 2*WSZ + wOff,
            bq + bOff, bk + bOff, bv + bOff, qb, kb, vb);
        tgemm_kernel<0,1><<<gP, 256, GEMM_SMEM>>>(pebf, wbf + 4*WSZ + wOff,
            nullptr, nullptr, pcb, NR, CC, CC);
        attn_kernel<<<gAtt, 256, ATTN_SMEM_BYTES>>>(qb, kb, vb, pcb, pu + bOff, pvv + bOff, obf);
        tgemm_kernel<2,0><<<gBig, 256, GEMM_SMEM>>>(obf, wbf + 3*WSZ + wOff,
            bo + bOff, h, h, BT, CC, CC);
        ln_kernel<<<BT, 256>>>(h, ybf, ln2g + bOff, ln2b + bOff);
        tgemm_kernel<1,1><<<gBig, 256, GEMM_SMEM>>>(ybf, wbf + 5*WSZ + wOff,
            b1 + bOff, nullptr, obf, BT, CC, CC);
        void* outp = (l == LNUM - 1) ? d_out : (void*)h;
        tgemm_kernel<2,0><<<gBig, 256, GEMM_SMEM>>>(obf, wbf + 6*WSZ + wOff,
            b2 + bOff, h, outp, BT, CC, CC);
    }
}

// round 13
// speedup vs baseline: 3.9907x; 1.0731x over previous
#include <cuda_runtime.h>
#include <cuda_bf16.h>
#include <math.h>
#include <stdint.h>

// ---------------- problem constants ----------------
#define LNUM 2
#define BB   4
#define TT   1000
#define CC   768
#define HH   12
#define DKK  64
#define WHALF 50         // band half-width (WIN//2)
#define NR   101         // relative positions actually reachable: -50..50
#define BT   (BB*TT)     // 4000 rows
#define WSZ  (LNUM*CC*CC)

// ---------------- device scratch (no allocs allowed) ----------------
__device__ float g_h[BT*CC];
__device__ __nv_bfloat16 g_ybf[BT*CC];        // LN output (GEMM A operand)
__device__ __nv_bfloat16 g_obf[BT*CC];        // attn out / gelu out (GEMM A operand)
__device__ __nv_bfloat16 g_qb[BT*CC];
__device__ __nv_bfloat16 g_kb[BT*CC];
__device__ __nv_bfloat16 g_vb[BT*CC];
__device__ __nv_bfloat16 g_pcb[NR*CC];        // pe @ Wp[l], bf16
__device__ __nv_bfloat16 g_pebf[NR*CC];       // positional table, bf16
__device__ __nv_bfloat16 g_wbf[7*WSZ];        // bf16 weights: Wq,Wk,Wv,Wo,Wp,W1,W2

// ---------------- small kernels ----------------
__global__ void init_h_kernel(const float* __restrict__ x) {
    int i = blockIdx.x * blockDim.x + threadIdx.x;
    if (i < BT*CC) g_h[i] = x[i] * 27.712812921102035f;  // sqrt(768)
}

// one kernel converts all 7 weight tensors fp32 -> bf16 (float4 vectorized)
__global__ void f2b_all_kernel(const float* __restrict__ s0, const float* __restrict__ s1,
                               const float* __restrict__ s2, const float* __restrict__ s3,
                               const float* __restrict__ s4, const float* __restrict__ s5,
                               const float* __restrict__ s6) {
    const int per = WSZ / 4;                       // float4 chunks per tensor
    int i4 = blockIdx.x * blockDim.x + threadIdx.x;
    int t = i4 / per;
    int off = i4 - t * per;
    const float* src = (t == 0) ? s0 : (t == 1) ? s1 : (t == 2) ? s2 :
                       (t == 3) ? s3 : (t == 4) ? s4 : (t == 5) ? s5 : s6;
    float4 vv = ((const float4*)src)[off];
    __nv_bfloat162 a, b;
    a.x = __float2bfloat16(vv.x); a.y = __float2bfloat16(vv.y);
    b.x = __float2bfloat16(vv.z); b.y = __float2bfloat16(vv.w);
    __nv_bfloat162* dst = (__nv_bfloat162*)(g_wbf + (size_t)t * WSZ);
    dst[off * 2]     = a;
    dst[off * 2 + 1] = b;
}

__global__ void pe_kernel() {
    int i = blockIdx.x * blockDim.x + threadIdx.x;
    if (i < NR*(CC/2)) {
        int r = i / (CC/2);
        int j = i % (CC/2);
        float div = expf(-(float)(2*j) * (9.210340371976184f / (float)CC)); // ln(10000)/C
        float ang = (float)(WHALF - r) * div;   // rel = -(r-50)
        g_pebf[r*CC + 2*j]     = __float2bfloat16(sinf(ang));
        g_pebf[r*CC + 2*j + 1] = __float2bfloat16(cosf(ang));
    }
}

// LayerNorm: fp32 in, bf16 out. float4 loads, bf16x4 stores. 1 row / block.
__global__ void ln_kernel(const float* __restrict__ in, __nv_bfloat16* __restrict__ out,
                          const float* __restrict__ g, const float* __restrict__ b) {
    const int row = blockIdx.x;
    const int tid = threadIdx.x;
    const float4* xr = (const float4*)(in + (size_t)row * CC);
    float4 vv = make_float4(0.f, 0.f, 0.f, 0.f);
    float s = 0.f, s2 = 0.f;
    if (tid < 192) {
        vv = xr[tid];
        s  = vv.x + vv.y + vv.z + vv.w;
        s2 = vv.x*vv.x + vv.y*vv.y + vv.z*vv.z + vv.w*vv.w;
    }
    __shared__ float sh[16];
    #pragma unroll
    for (int o = 16; o; o >>= 1) {
        s  += __shfl_xor_sync(0xffffffffu, s,  o);
        s2 += __shfl_xor_sync(0xffffffffu, s2, o);
    }
    int w = tid >> 5;
    if ((tid & 31) == 0) { sh[w] = s; sh[8 + w] = s2; }
    __syncthreads();
    s = 0.f; s2 = 0.f;
    #pragma unroll
    for (int i = 0; i < 8; i++) { s += sh[i]; s2 += sh[8 + i]; }
    float mean = s * (1.f / CC);
    float var  = s2 * (1.f / CC) - mean * mean;
    float rstd = rsqrtf(var + 1e-5f);
    if (tid < 192) {
        float4 g4 = ((const float4*)g)[tid];
        float4 b4 = ((const float4*)b)[tid];
        __nv_bfloat162 p0, p1;
        p0.x = __float2bfloat16((vv.x - mean) * rstd * g4.x + b4.x);
        p0.y = __float2bfloat16((vv.y - mean) * rstd * g4.y + b4.y);
        p1.x = __float2bfloat16((vv.z - mean) * rstd * g4.z + b4.z);
        p1.y = __float2bfloat16((vv.w - mean) * rstd * g4.w + b4.w);
        uint2 u;
        u.x = *(uint32_t*)&p0;
        u.y = *(uint32_t*)&p1;
        ((uint2*)(out + (size_t)row * CC))[tid] = u;
    }
}

// ---------------- mma / ldmatrix / cp.async helpers ----------------
__device__ __forceinline__ void mma_bf16(float c[4], const uint4& a, uint32_t b0, uint32_t b1) {
    asm volatile(
        "mma.sync.aligned.m16n8k16.row.col.f32.bf16.bf16.f32 "
        "{%0,%1,%2,%3}, {%4,%5,%6,%7}, {%8,%9}, {%0,%1,%2,%3};"
        : "+f"(c[0]), "+f"(c[1]), "+f"(c[2]), "+f"(c[3])
        : "r"(a.x), "r"(a.y), "r"(a.z), "r"(a.w), "r"(b0), "r"(b1));
}
__device__ __forceinline__ void ldsm_x4(uint4& d, uint32_t addr) {
    asm volatile("ldmatrix.sync.aligned.m8n8.x4.shared.b16 {%0,%1,%2,%3}, [%4];"
                 : "=r"(d.x), "=r"(d.y), "=r"(d.z), "=r"(d.w) : "r"(addr));
}
__device__ __forceinline__ void ldsm_x4_t(uint4& d, uint32_t addr) {
    asm volatile("ldmatrix.sync.aligned.m8n8.x4.trans.shared.b16 {%0,%1,%2,%3}, [%4];"
                 : "=r"(d.x), "=r"(d.y), "=r"(d.z), "=r"(d.w) : "r"(addr));
}
__device__ __forceinline__ void cp16(uint32_t dst, const void* src, int srcsize) {
    asm volatile("cp.async.cg.shared.global [%0], [%1], 16, %2;\n"
                 :: "r"(dst), "l"(src), "r"(srcsize));
}
__device__ __forceinline__ void cp_commit() {
    asm volatile("cp.async.commit_group;\n");
}
template<int N> __device__ __forceinline__ void cp_wait() {
    asm volatile("cp.async.wait_group %0;\n" :: "n"(N));
}

__device__ __forceinline__ float gelu_f(float x) {
    float x3 = x * x * x;
    return 0.5f * x * (1.f + tanhf(0.7978845608028654f * (x + 0.044715f * x3)));
}

// ---------------- bf16 tensor-core GEMM, 3-stage cp.async (R9 proven tiling) ----------------
// C(MxN) = A(MxK) @ B(KxN) [+bias] [epilogue]. BM=128, BN=64, BK=32 (bf16).
// 256 threads = 8 warps (4 row x 2 col), warp tile 32x32.
// A staged m-major, row stride 20 u32 -> CF ldmatrix.
// B staged k-major, row stride 36 u32 -> CF ldmatrix.trans.
#define AST2 20
#define BST2 36
#define STG_A (128*AST2)   // 2560 u32
#define STG_B (32*BST2)    // 1152 u32
#define GEMM_SMEM (3*(STG_A+STG_B)*4)   // 44544 bytes

template<int EPI, int OUTBF>
__device__ __forceinline__ void gemm_body(
        const __nv_bfloat16* __restrict__ A, const __nv_bfloat16* __restrict__ Bm,
        const float* __restrict__ bias, const float* __restrict__ resid,
        void* __restrict__ Cm, int M, int N, int K, int row0, int col0) {
    extern __shared__ uint32_t smu[];
    const uint32_t smem_base = (uint32_t)__cvta_generic_to_shared(smu);

    const int tid  = threadIdx.x;
    const int warp = tid >> 5;
    const int lane = tid & 31;
    const int g    = lane >> 2;
    const int t    = lane & 3;
    const int wr   = warp >> 1;    // 0..3 : 32 M-rows
    const int wc   = warp & 1;     // 0..1 : 32 N-cols

    float acc[2][4][4];
    #pragma unroll
    for (int i = 0; i < 2; i++)
        #pragma unroll
        for (int j = 0; j < 4; j++)
            #pragma unroll
            for (int r = 0; r < 4; r++) acc[i][j][r] = 0.f;

    const int a_r = tid >> 2, a_c = tid & 3;
    const int b_r = tid >> 3, b_c = tid & 7;

#define LOADS(s_) do {                                                              \
        const int k0_ = (s_) * 32;                                                  \
        uint32_t* Ab_ = smu + ((s_) % 3) * (STG_A + STG_B);                         \
        uint32_t* Bb_ = Ab_ + STG_A;                                                \
        _Pragma("unroll")                                                           \
        for (int i_ = 0; i_ < 2; i_++) {                                            \
            int r_ = a_r + i_ * 64;                                                 \
            int gr_ = row0 + r_;                                                    \
            int ok_ = (gr_ < M) ? 16 : 0;                                           \
            const __nv_bfloat16* src_ = A + (size_t)(ok_ ? gr_ : 0) * K + k0_ + a_c * 8; \
            cp16((uint32_t)__cvta_generic_to_shared(Ab_ + r_ * AST2 + a_c * 4), src_, ok_); \
        }                                                                           \
        {                                                                           \
            const __nv_bfloat16* src_ = Bm + (size_t)(k0_ + b_r) * N + col0 + b_c * 8;   \
            cp16((uint32_t)__cvta_generic_to_shared(Bb_ + b_r * BST2 + b_c * 4), src_, 16); \
        }                                                                           \
    } while (0)

    const int steps = K >> 5;
    LOADS(0); cp_commit();
    LOADS(1); cp_commit();

    const int a_lane_off = (lane & 15) * AST2 + (lane >> 4) * 4;
    const int b_lane_off = (lane & 15) * BST2 + wc * 16 + (lane >> 4) * 4;

    for (int s = 0; s < steps; s++) {
        cp_wait<1>();
        __syncthreads();
        if (s + 2 < steps) LOADS(s + 2);
        cp_commit();

        const uint32_t bufo = (uint32_t)((s % 3) * (STG_A + STG_B));
        const uint32_t abase = smem_base + (bufo + wr * 32 * AST2 + a_lane_off) * 4;
        const uint32_t bbase = smem_base + (bufo + STG_A + b_lane_off) * 4;

        #pragma unroll
        for (int ch = 0; ch < 2; ch++) {
            uint4 af[2];
            #pragma unroll
            for (int i = 0; i < 2; i++)
                ldsm_x4(af[i], abase + (i * 16 * AST2 + ch * 8) * 4);
            uint4 bq[2];
            #pragma unroll
            for (int jj = 0; jj < 2; jj++)
                ldsm_x4_t(bq[jj], bbase + (ch * 16 * BST2 + jj * 8) * 4);
            #pragma unroll
            for (int i = 0; i < 2; i++) {
                mma_bf16(acc[i][0], af[i], bq[0].x, bq[0].y);
                mma_bf16(acc[i][1], af[i], bq[0].z, bq[0].w);
                mma_bf16(acc[i][2], af[i], bq[1].x, bq[1].y);
                mma_bf16(acc[i][3], af[i], bq[1].z, bq[1].w);
            }
        }
    }
#undef LOADS

    __syncthreads();

    #pragma unroll
    for (int i = 0; i < 2; i++) {
        int rbase = row0 + wr * 32 + i * 16 + g;
        #pragma unroll
        for (int j = 0; j < 4; j++) {
            int col = col0 + wc * 32 + j * 8 + t * 2;
            float bx = 0.f, by = 0.f;
            if (bias) { bx = bias[col]; by = bias[col + 1]; }
            #pragma unroll
            for (int hh = 0; hh < 2; hh++) {
                int row = rbase + hh * 8;
                if (row < M) {
                    float c0 = acc[i][j][hh * 2 + 0] + bx;
                    float c1 = acc[i][j][hh * 2 + 1] + by;
                    if (EPI == 1) { c0 = gelu_f(c0); c1 = gelu_f(c1); }
                    if (EPI == 2) {
                        float2 rv = *(const float2*)(resid + (size_t)row * N + col);
                        c0 += rv.x; c1 += rv.y;
                    }
                    if (OUTBF) {
                        __nv_bfloat162 p;
                        p.x = __float2bfloat16(c0);
                        p.y = __float2bfloat16(c1);
                        *(__nv_bfloat162*)((__nv_bfloat16*)Cm + (size_t)row * N + col) = p;
                    } else {
                        *(float2*)((float*)Cm + (size_t)row * N + col) = make_float2(c0, c1);
                    }
                }
            }
        }
    }
}

template<int EPI, int OUTBF>
__global__ void __launch_bounds__(256)
tgemm_kernel(const __nv_bfloat16* __restrict__ A, const __nv_bfloat16* __restrict__ Bm,
             const float* __restrict__ bias, const float* __restrict__ resid,
             void* __restrict__ Cm, int M, int N, int K) {
    gemm_body<EPI, OUTBF>(A, Bm, bias, resid, Cm, M, N, K,
                          blockIdx.y * 128, blockIdx.x * 64);
}

// fused QKV + Wp: blockIdx.x in [0,48). [0,36): sel=x/12 picks {q,k,v};
// [36,48): the tiny pe@Wp GEMM (M=101) on blockIdx.y==0 only.
__global__ void __launch_bounds__(256)
qkv_kernel(const __nv_bfloat16* __restrict__ A,
           const __nv_bfloat16* __restrict__ Bq, const __nv_bfloat16* __restrict__ Bk,
           const __nv_bfloat16* __restrict__ Bv, const __nv_bfloat16* __restrict__ Bp,
           const float* __restrict__ bq, const float* __restrict__ bk,
           const float* __restrict__ bv,
           __nv_bfloat16* __restrict__ Cq, __nv_bfloat16* __restrict__ Ck,
           __nv_bfloat16* __restrict__ Cv,
           const __nv_bfloat16* __restrict__ pe, __nv_bfloat16* __restrict__ Cp) {
    int xx = blockIdx.x;
    if (xx < 36) {
        int sel = xx / 12;
        int colblk = xx % 12;
        const __nv_bfloat16* Bm = (sel == 0) ? Bq : (sel == 1) ? Bk : Bv;
        const float* bias       = (sel == 0) ? bq : (sel == 1) ? bk : bv;
        __nv_bfloat16* Cm       = (sel == 0) ? Cq : (sel == 1) ? Ck : Cv;
        gemm_body<0, 1>(A, Bm, bias, nullptr, Cm, BT, CC, CC,
                        blockIdx.y * 128, colblk * 64);
    } else {
        if (blockIdx.y != 0) return;
        int colblk = xx - 36;
        gemm_body<0, 1>(pe, Bp, nullptr, nullptr, Cp, NR, CC, CC,
                        0, colblk * 64);
    }
}

// ---------------- banded rel-pos attention (bf16 tensor-core) ----------------
#define TQ 16

#define U_KV 0            // 128 rows x 36 u32 (K, then V)
#define U_QU 4608         // 16 x 36
#define U_QV 5184         // 16 x 36
#define U_PS 5760         // 104 x 36
#define U_S1 9504         // fp32 16 x 132
#define U_SC 11616        // fp32 16 x 104
#define U_AT 13280        // bf16 16 x 68 u32 (= 136 bf16 cols)
#define ATTN_U32 14368
#define ATTN_SMEM_BYTES (ATTN_U32*4)

__global__ void __launch_bounds__(256)
attn_kernel(const __nv_bfloat16* __restrict__ q, const __nv_bfloat16* __restrict__ k,
            const __nv_bfloat16* __restrict__ v, const __nv_bfloat16* __restrict__ pc,
            const float* __restrict__ pu, const float* __restrict__ pv,
            __nv_bfloat16* __restrict__ o) {
    extern __shared__ uint32_t su[];
    uint32_t* KV  = su + U_KV;
    uint32_t* QUb = su + U_QU;
    uint32_t* QVb = su + U_QV;
    uint32_t* PSb = su + U_PS;
    float*    S1  = (float*)(su + U_S1);
    float*    SC  = (float*)(su + U_SC);
    uint32_t* AT  = su + U_AT;
    const uint32_t smem_base = (uint32_t)__cvta_generic_to_shared(su);

    const int b  = blockIdx.z;
    const int h  = blockIdx.y;
    const int t0 = blockIdx.x * TQ;
    const int sb = t0 - WHALF;
    const int tid = threadIdx.x;
    const int warp = tid >> 5, lane = tid & 31;
    const int g = lane >> 2, t4 = lane & 3;

    // ---- phase 1: stage QU/QV, K, P
    for (int e = tid; e < TQ * 32; e += 256) {
        int qi = e >> 5, cu = e & 31;
        int tt = t0 + qi;
        float f0 = 0.f, f1 = 0.f;
        if (tt < TT) {
            uint32_t raw = *(const uint32_t*)(q + ((size_t)(b*TT+tt))*CC + h*DKK + cu*2);
            __nv_bfloat162 p = *(__nv_bfloat162*)&raw;
            f0 = __bfloat162float(p.x); f1 = __bfloat162float(p.y);
        }
        float u0 = pu[h*DKK + cu*2], u1 = pu[h*DKK + cu*2 + 1];
        float w0 = pv[h*DKK + cu*2], w1 = pv[h*DKK + cu*2 + 1];
        __nv_bfloat162 a, c;
        a.x = __float2bfloat16(f0 + u0); a.y = __float2bfloat16(f1 + u1);
        c.x = __float2bfloat16(f0 + w0); c.y = __float2bfloat16(f1 + w1);
        QUb[qi*36 + cu] = *(uint32_t*)&a;
        QVb[qi*36 + cu] = *(uint32_t*)&c;
    }
    for (int e = tid; e < 120 * 8; e += 256) {
        int si = e >> 3, c = e & 7;
        int s = sb + si;
        uint4 kk = make_uint4(0,0,0,0);
        if (s >= 0 && s < TT) kk = *(const uint4*)(k + ((size_t)(b*TT+s))*CC + h*DKK + c*8);
        *(uint4*)(KV + si*36 + c*4) = kk;
    }
    for (int e = tid; e < 104 * 8; e += 256) {
        int r = e >> 3, c = e & 7;
        uint4 pp = make_uint4(0,0,0,0);
        if (r < NR) pp = *(const uint4*)(pc + (size_t)r*CC + h*DKK + c*8);
        *(uint4*)(PSb + r*36 + c*4) = pp;
    }
    __syncthreads();

    // ---- phase 2: score GEMMs (A fragments hoisted)
    {
        uint4 af[4];
        #pragma unroll
        for (int ch = 0; ch < 4; ch++) {
            af[ch].x = QUb[g*36 + ch*8 + t4];
            af[ch].y = QUb[(g+8)*36 + ch*8 + t4];
            af[ch].z = QUb[g*36 + ch*8 + t4 + 4];
            af[ch].w = QUb[(g+8)*36 + ch*8 + t4 + 4];
        }
        for (int nt = warp; nt < 15; nt += 8) {
            float c[4] = {0.f, 0.f, 0.f, 0.f};
            #pragma unroll
            for (int ch = 0; ch < 4; ch++) {
                uint32_t b0 = KV[(nt*8+g)*36 + ch*8 + t4];
                uint32_t b1 = KV[(nt*8+g)*36 + ch*8 + t4 + 4];
                mma_bf16(c, af[ch], b0, b1);
            }
            *(float2*)(S1 + g*132 + nt*8 + 2*t4)     = make_float2(c[0], c[1]);
            *(float2*)(S1 + (g+8)*132 + nt*8 + 2*t4) = make_float2(c[2], c[3]);
        }
        #pragma unroll
        for (int ch = 0; ch < 4; ch++) {
            af[ch].x = QVb[g*36 + ch*8 + t4];
            af[ch].y = QVb[(g+8)*36 + ch*8 + t4];
            af[ch].z = QVb[g*36 + ch*8 + t4 + 4];
            af[ch].w = QVb[(g+8)*36 + ch*8 + t4 + 4];
        }
        for (int nt = warp; nt < 13; nt += 8) {
            float c[4] = {0.f, 0.f, 0.f, 0.f};
            #pragma unroll
            for (int ch = 0; ch < 4; ch++) {
                uint32_t b0 = PSb[(nt*8+g)*36 + ch*8 + t4];
                uint32_t b1 = PSb[(nt*8+g)*36 + ch*8 + t4 + 4];
                mma_bf16(c, af[ch], b0, b1);
            }
            *(float2*)(SC + g*104 + nt*8 + 2*t4)     = make_float2(c[0], c[1]);
            *(float2*)(SC + (g+8)*104 + nt*8 + 2*t4) = make_float2(c[2], c[3]);
        }
    }
    __syncthreads();

    // ---- phase 3a: combine+mask -> SC ; zero AT ; stage V (overwrites K)
    for (int e = tid; e < TQ * NR; e += 256) {
        int qi = e & 15, r = e >> 4;
        int tt = t0 + qi, s = tt + r - WHALF;
        float val = -1e30f;
        if (tt < TT && s >= 0 && s < TT)
            val = (S1[qi*132 + qi + r] + SC[qi*104 + r]) * 0.125f;
        SC[qi*104 + r] = val;
    }
    for (int e = tid; e < TQ * 68; e += 256) AT[e] = 0u;
    for (int e = tid; e < 128 * 8; e += 256) {
        int si = e >> 3, c = e & 7;
        int s = sb + si;
        uint4 vv = make_uint4(0,0,0,0);
        if (si < 120 && s >= 0 && s < TT)
            vv = *(const uint4*)(v + ((size_t)(b*TT+s))*CC + h*DKK + c*8);
        *(uint4*)(KV + si*36 + c*4) = vv;
    }
    __syncthreads();

    // ---- phase 3b: softmax (serial, 16 rows)
    if (tid < TQ) {
        float* srow = SC + tid * 104;
        float m = -1e30f;
        for (int r = 0; r < NR; r++) m = fmaxf(m, srow[r]);
        float sum = 0.f;
        for (int r = 0; r < NR; r++) { float ev = __expf(srow[r] - m); srow[r] = ev; sum += ev; }
        float inv = 1.f / sum;
        for (int r = 0; r < NR; r++) srow[r] *= inv;
    }
    __syncthreads();

    // ---- phase 3c: scatter bf16 weights into shifted AT
    for (int e = tid; e < TQ * NR; e += 256) {
        int qi = e & 15, r = e >> 4;
        ((__nv_bfloat16*)AT)[qi*136 + qi + r] = __float2bfloat16(SC[qi*104 + r]);
    }
    __syncthreads();

    // ---- phase 4: O = AT(16x128) @ V(128x64); warps 0-3, n16 each
    if (warp < 4) {
        int n0 = warp * 16;
        float c0[4] = {0.f,0.f,0.f,0.f};
        float c1[4] = {0.f,0.f,0.f,0.f};
        uint32_t vbase = smem_base + (U_KV + (lane & 15)*36 + (n0 >> 1) + (lane >> 4)*4) * 4;
        #pragma unroll
        for (int ch = 0; ch < 8; ch++) {
            uint4 a;
            a.x = AT[g*68 + ch*8 + t4];
            a.y = AT[(g+8)*68 + ch*8 + t4];
            a.z = AT[g*68 + ch*8 + t4 + 4];
            a.w = AT[(g+8)*68 + ch*8 + t4 + 4];
            uint4 bq;
            ldsm_x4_t(bq, vbase + (ch * 16 * 36) * 4);
            mma_bf16(c0, a, bq.x, bq.y);
            mma_bf16(c1, a, bq.z, bq.w);
        }
        int tg0 = t0 + g, tg1 = t0 + g + 8;
        if (tg0 < TT) {
            __nv_bfloat16* orow = o + ((size_t)(b*TT+tg0))*CC + h*DKK;
            __nv_bfloat162 p;
            p.x = __float2bfloat16(c0[0]); p.y = __float2bfloat16(c0[1]);
            *(__nv_bfloat162*)(orow + n0 + 2*t4) = p;
            p.x = __float2bfloat16(c1[0]); p.y = __float2bfloat16(c1[1]);
            *(__nv_bfloat162*)(orow + n0 + 8 + 2*t4) = p;
        }
        if (tg1 < TT) {
            __nv_bfloat16* orow = o + ((size_t)(b*TT+tg1))*CC + h*DKK;
            __nv_bfloat162 p;
            p.x = __float2bfloat16(c0[2]); p.y = __float2bfloat16(c0[3]);
            *(__nv_bfloat162*)(orow + n0 + 2*t4) = p;
            p.x = __float2bfloat16(c1[2]); p.y = __float2bfloat16(c1[3]);
            *(__nv_bfloat162*)(orow + n0 + 8 + 2*t4) = p;
        }
    }
}

// ---------------- driver ----------------
extern "C" void kernel_launch(void* const* d_in, const int* in_sizes, int n_in,
                              void* d_out, int out_size) {
    const float* x    = (const float*)d_in[0];
    const float* Wq   = (const float*)d_in[1];
    const float* bq   = (const float*)d_in[2];
    const float* Wk   = (const float*)d_in[3];
    const float* bk   = (const float*)d_in[4];
    const float* Wv   = (const float*)d_in[5];
    const float* bv   = (const float*)d_in[6];
    const float* Wo   = (const float*)d_in[7];
    const float* bo   = (const float*)d_in[8];
    const float* Wp   = (const float*)d_in[9];
    const float* pu   = (const float*)d_in[10];
    const float* pvv  = (const float*)d_in[11];
    const float* ln1g = (const float*)d_in[12];
    const float* ln1b = (const float*)d_in[13];
    const float* ln2g = (const float*)d_in[14];
    const float* ln2b = (const float*)d_in[15];
    const float* W1   = (const float*)d_in[16];
    const float* b1   = (const float*)d_in[17];
    const float* W2   = (const float*)d_in[18];
    const float* b2   = (const float*)d_in[19];
    // d_in[20] = att_mask: fixed band |i-j|>50, handled analytically.

    float* h;
    __nv_bfloat16 *ybf, *obf, *qb, *kb, *vb, *pcb, *pebf, *wbf;
    cudaGetSymbolAddress((void**)&h,    g_h);
    cudaGetSymbolAddress((void**)&ybf,  g_ybf);
    cudaGetSymbolAddress((void**)&obf,  g_obf);
    cudaGetSymbolAddress((void**)&qb,   g_qb);
    cudaGetSymbolAddress((void**)&kb,   g_kb);
    cudaGetSymbolAddress((void**)&vb,   g_vb);
    cudaGetSymbolAddress((void**)&pcb,  g_pcb);
    cudaGetSymbolAddress((void**)&pebf, g_pebf);
    cudaGetSymbolAddress((void**)&wbf,  g_wbf);

    cudaFuncSetAttribute(tgemm_kernel<1,1>, cudaFuncAttributeMaxDynamicSharedMemorySize, GEMM_SMEM);
    cudaFuncSetAttribute(tgemm_kernel<2,0>, cudaFuncAttributeMaxDynamicSharedMemorySize, GEMM_SMEM);
    cudaFuncSetAttribute(qkv_kernel,        cudaFuncAttributeMaxDynamicSharedMemorySize, GEMM_SMEM);
    cudaFuncSetAttribute(attn_kernel,       cudaFuncAttributeMaxDynamicSharedMemorySize, ATTN_SMEM_BYTES);

    f2b_all_kernel<<<7 * (WSZ / 4) / 256, 256>>>(Wq, Wk, Wv, Wo, Wp, W1, W2);
    init_h_kernel<<<(BT*CC + 255) / 256, 256>>>(x);
    pe_kernel<<<(NR*(CC/2) + 255) / 256, 256>>>();

    dim3 gBig(CC / 64, (BT + 127) / 128);        // (12, 32)
    dim3 gQKV(48, (BT + 127) / 128);             // (48, 32): qkv + fused Wp
    dim3 gAtt((TT + TQ - 1) / TQ, HH, BB);       // (63, 12, 4)

    for (int l = 0; l < LNUM; l++) {
        size_t wOff = (size_t)l * CC * CC;
        size_t bOff = (size_t)l * CC;

        ln_kernel<<<BT, 256>>>(h, ybf, ln1g + bOff, ln1b + bOff);
        qkv_kernel<<<gQKV, 256, GEMM_SMEM>>>(ybf,
            wbf + 0*WSZ + wOff, wbf + 1*WSZ + wOff, wbf + 2*WSZ + wOff,
            wbf + 4*WSZ + wOff,
            bq + bOff, bk + bOff, bv + bOff, qb, kb, vb, pebf, pcb);
        attn_kernel<<<gAtt, 256, ATTN_SMEM_BYTES>>>(qb, kb, vb, pcb, pu + bOff, pvv + bOff, obf);
        tgemm_kernel<2,0><<<gBig, 256, GEMM_SMEM>>>(obf, wbf + 3*WSZ + wOff,
            bo + bOff, h, h, BT, CC, CC);
        ln_kernel<<<BT, 256>>>(h, ybf, ln2g + bOff, ln2b + bOff);
        tgemm_kernel<1,1><<<gBig, 256, GEMM_SMEM>>>(ybf, wbf + 5*WSZ + wOff,
            b1 + bOff, nullptr, obf, BT, CC, CC);
        void* outp = (l == LNUM - 1) ? d_out : (void*)h;
        tgemm_kernel<2,0><<<gBig, 256, GEMM_SMEM>>>(obf, wbf + 6*WSZ + wOff,
            b2 + bOff, h, outp, BT, CC, CC);
    }
}